// round 3
// baseline (speedup 1.0000x reference)
#include <cuda_runtime.h>
#include <cstdint>

#define BATCH 16
#define DIM   256
#define TLEN  4096
#define NROWS (BATCH*TLEN)   // 65536
#define KCODES 1024
#define ZQ_ELEMS (BATCH*DIM*TLEN)  // 16777216

typedef unsigned long long ull;

// ---------------- device scratch (no allocations allowed) ----------------
__device__ float d_e2[KCODES];
__device__ int   d_counts[KCODES];
__device__ float d_sumd2;
__device__ int   d_idx[NROWS];

// ---------------- helpers ----------------
__device__ __forceinline__ void fma2(ull &acc, ull a, ull b) {
    // packed 2x fp32 FMA (sm_100+): lo += a.lo*b.lo, hi += a.hi*b.hi
    asm volatile("fma.rn.f32x2 %0, %1, %2, %0;" : "+l"(acc) : "l"(a), "l"(b));
}
__device__ __forceinline__ uint32_t sm_u32(const void* p) {
    return (uint32_t)__cvta_generic_to_shared(p);
}
__device__ __forceinline__ void cp16(void* dst, const void* src) {
    asm volatile("cp.async.cg.shared.global [%0], [%1], 16;" :: "r"(sm_u32(dst)), "l"(src));
}

// ---------------- init: zero stats, codeword norms ----------------
__global__ void vq_init(const float* __restrict__ embed) {
    int k = blockIdx.x * 256 + threadIdx.x;
    if (k < KCODES) {
        const float4* row = (const float4*)(embed + (size_t)k * DIM);
        float s = 0.f;
        #pragma unroll 8
        for (int i = 0; i < DIM/4; i++) {
            float4 v = row[i];
            s += v.x*v.x + v.y*v.y + v.z*v.z + v.w*v.w;
        }
        d_e2[k] = s;
        d_counts[k] = 0;
    }
    if (k == 0) d_sumd2 = 0.f;
}

// ---------------- fused distance-GEMM + argmin ----------------
// block: 64 rows (t-positions). 256 threads = 8 warps.
// warp w owns rows m0 = 8*w (A-operand broadcasts within warp).
// lane owns 4 columns per 128-col chunk: n = lane + 32*j.
// acc[r][j] is f32x2: lo = sum over even k, hi = sum over odd k.
#define XS_S 260                 // 256 + 4 pad (words)
#define ES_S 68                  // 64 + 4 pad (words)
#define ES_TILE (128*ES_S)       // one k-tile of the codebook chunk
#define N_TILES 32               // 8 col-chunks x 4 k-tiles

__global__ __launch_bounds__(256, 1)
void vq_argmin(const float* __restrict__ x, const float* __restrict__ embed) {
    extern __shared__ float sm[];
    float* xs  = sm;                          // [64][XS_S]
    float* es  = sm + 64*XS_S;                // [2][ES_TILE]
    float* x2s = es + 2*ES_TILE;              // [64]
    float* bsum = x2s + 64;                   // [1]

    const int tid  = threadIdx.x;
    const int wid  = tid >> 5;
    const int lane = tid & 31;
    const int row0 = blockIdx.x * 64;
    const int b    = row0 >> 12;
    const int t0   = row0 & (TLEN - 1);
    const int m0   = wid * 8;

    if (tid == 0) *bsum = 0.f;

    // stage x tile (transpose: global is (b, d, t), smem is [m][k])
    {
        const float* xb = x + (size_t)b * DIM * TLEN + t0;
        for (int i = tid; i < 64 * DIM; i += 256) {
            int m = i & 63, d = i >> 6;
            xs[m * XS_S + d] = xb[(size_t)d * TLEN + m];
        }
    }
    __syncthreads();

    // per-row squared norms (needed only for the loss)
    if (tid < 64) {
        float s = 0.f;
        const float* r = xs + tid * XS_S;
        #pragma unroll 8
        for (int k = 0; k < DIM; k++) s += r[k] * r[k];
        x2s[tid] = s;
    }

    float bestScore[8];
    int   bestIdx[8];
    #pragma unroll
    for (int r = 0; r < 8; r++) { bestScore[r] = INFINITY; bestIdx[r] = 0; }

    ull acc[8][4];

    // prologue: load tile 0
    {
        const float* src0 = embed;
        #pragma unroll
        for (int j = 0; j < 8; j++) {
            int i = tid + 256 * j;
            int n = i & 127, k4 = i >> 7;
            cp16(es + n * ES_S + k4 * 4, src0 + (size_t)n * DIM + k4 * 4);
        }
        asm volatile("cp.async.commit_group;");
    }

    for (int tt = 0; tt < N_TILES; tt++) {
        const int kt = tt & 3, c = tt >> 2, buf = tt & 1;

        if (tt + 1 < N_TILES) {
            const int c2 = (tt + 1) >> 2, kt2 = (tt + 1) & 3, buf2 = (tt + 1) & 1;
            const float* src0 = embed + (size_t)(c2 * 128) * DIM + kt2 * 64;
            float* dst0 = es + buf2 * ES_TILE;
            #pragma unroll
            for (int j = 0; j < 8; j++) {
                int i = tid + 256 * j;
                int n = i & 127, k4 = i >> 7;
                cp16(dst0 + n * ES_S + k4 * 4, src0 + (size_t)n * DIM + k4 * 4);
            }
            asm volatile("cp.async.commit_group;");
            asm volatile("cp.async.wait_group 1;");
        } else {
            asm volatile("cp.async.wait_group 0;");
        }
        __syncthreads();

        if (kt == 0) {
            #pragma unroll
            for (int r = 0; r < 8; r++)
                #pragma unroll
                for (int j = 0; j < 4; j++) acc[r][j] = 0ull;
        }

        const float* eb = es + buf * ES_TILE;
        const float* xk = xs + kt * 64;

        #pragma unroll 4
        for (int k4 = 0; k4 < 16; k4++) {
            ulonglong2 bv[4];
            #pragma unroll
            for (int j = 0; j < 4; j++)
                bv[j] = *(const ulonglong2*)(eb + (lane + 32 * j) * ES_S + k4 * 4);
            #pragma unroll
            for (int r = 0; r < 8; r++) {
                ulonglong2 av = *(const ulonglong2*)(xk + (m0 + r) * XS_S + k4 * 4);
                #pragma unroll
                for (int j = 0; j < 4; j++) {
                    fma2(acc[r][j], av.x, bv[j].x);
                    fma2(acc[r][j], av.y, bv[j].y);
                }
            }
        }

        if (kt == 3) {
            // finalize this 128-column chunk: score = ||e||^2 - 2*dot
            #pragma unroll
            for (int j = 0; j < 4; j++) {
                int ng = c * 128 + lane + 32 * j;
                float e2v = __ldg(&d_e2[ng]);
                #pragma unroll
                for (int r = 0; r < 8; r++) {
                    float lo = __uint_as_float((unsigned)(acc[r][j] & 0xffffffffull));
                    float hi = __uint_as_float((unsigned)(acc[r][j] >> 32));
                    float sc = fmaf(-2.f, lo + hi, e2v);
                    if (sc < bestScore[r]) { bestScore[r] = sc; bestIdx[r] = ng; }
                }
            }
        }
        __syncthreads();
    }

    // reduce argmin across the 32 lanes that share each row
    float wsum = 0.f;
    #pragma unroll
    for (int r = 0; r < 8; r++) {
        float s = bestScore[r];
        int   ix = bestIdx[r];
        #pragma unroll
        for (int off = 16; off; off >>= 1) {
            float s2 = __shfl_down_sync(0xffffffffu, s, off);
            int   i2 = __shfl_down_sync(0xffffffffu, ix, off);
            if (s2 < s || (s2 == s && i2 < ix)) { s = s2; ix = i2; }
        }
        if (lane == 0) {
            int row = row0 + m0 + r;
            d_idx[row] = ix;
            atomicAdd(&d_counts[ix], 1);
            wsum += x2s[m0 + r] + s;   // ||x - e||^2
        }
    }
    if (lane == 0) atomicAdd(bsum, wsum);
    __syncthreads();
    if (tid == 0) atomicAdd(&d_sumd2, *bsum);
}

// ---------------- gather codewords, write z_q in (B, D, T) layout ----------------
__global__ __launch_bounds__(256)
void vq_gather(const float* __restrict__ embed, float* __restrict__ out) {
    __shared__ float sh[32 * 257];
    __shared__ int sidx[32];
    const int tid = threadIdx.x;
    const int row0 = blockIdx.x * 32;
    const int b = row0 >> 12, t0 = row0 & (TLEN - 1);

    if (tid < 32) sidx[tid] = d_idx[row0 + tid];
    __syncthreads();

    for (int i = tid; i < 32 * DIM; i += 256) {
        int r = i >> 8, d = i & 255;
        sh[r * 257 + d] = embed[(size_t)sidx[r] * DIM + d];
    }
    __syncthreads();

    float* ob = out + (size_t)b * DIM * TLEN + t0;
    for (int i = tid; i < 32 * DIM; i += 256) {
        int tl = i & 31, d = i >> 5;
        ob[(size_t)d * TLEN + tl] = sh[tl * 257 + d];
    }
}

// ---------------- scalars: loss, kldiv_r, perplexity ----------------
__global__ void vq_finalize(float* __restrict__ out, int out_size) {
    __shared__ float red[32];
    const int tid = threadIdx.x;   // 1024 threads
    float p = (float)d_counts[tid] * (1.0f / (float)NROWS);
    float term = p * logf(p + 1e-10f);
    #pragma unroll
    for (int off = 16; off; off >>= 1) term += __shfl_down_sync(0xffffffffu, term, off);
    if ((tid & 31) == 0) red[tid >> 5] = term;
    __syncthreads();
    if (tid < 32) {
        float v = red[tid];
        #pragma unroll
        for (int off = 16; off; off >>= 1) v += __shfl_down_sync(0xffffffffu, v, off);
        if (tid == 0) {
            float entropy = -v;
            float perp = expf(entropy);
            float loss = 1.25f * d_sumd2 * (1.0f / (float)ZQ_ELEMS);
            float kld  = (float)(log((double)KCODES) * (double)TLEN);
            int Z = ZQ_ELEMS;
            if (Z < out_size) out[Z] = loss;
            for (int i = 0; i < BATCH; i++)
                if (Z + 1 + i < out_size) out[Z + 1 + i] = kld;
            if (Z + 17 < out_size) out[Z + 17] = perp;
        }
    }
}

// ---------------- launcher ----------------
extern "C" void kernel_launch(void* const* d_in, const int* in_sizes, int n_in,
                              void* d_out, int out_size) {
    const float* a0 = (const float*)d_in[0];
    const float* a1 = (const float*)d_in[1];
    const float* x;
    const float* embed;
    if (in_sizes[0] == ZQ_ELEMS) { x = a0; embed = a1; }
    else                         { x = a1; embed = a0; }
    float* out = (float*)d_out;

    const int SMEM_BYTES = (64 * XS_S + 2 * ES_TILE + 64 + 16) * 4;
    cudaFuncSetAttribute(vq_argmin, cudaFuncAttributeMaxDynamicSharedMemorySize, SMEM_BYTES);

    vq_init<<<(KCODES + 255) / 256, 256>>>(embed);
    vq_argmin<<<NROWS / 64, 256, SMEM_BYTES>>>(x, embed);
    vq_gather<<<NROWS / 32, 256>>>(embed, out);
    vq_finalize<<<1, KCODES>>>(out, out_size);
}

// round 8
// speedup vs baseline: 1.7688x; 1.7688x over previous
#include <cuda_runtime.h>
#include <cstdint>

#define BATCH 16
#define DIM   256
#define TLEN  4096
#define NROWS (BATCH*TLEN)         // 65536
#define KCODES 1024
#define ZQ_ELEMS (BATCH*DIM*TLEN)  // 16777216

// ---------------- device scratch (static; no allocations allowed) ----------
__device__ float d_e2[KCODES];
__device__ int   d_counts[KCODES];
__device__ float d_sumd2;
__device__ int   d_idx[NROWS];
__device__ float d_x2[NROWS];
// packed in mma-fragment order (see pack kernels)
__device__ float d_xhi[(size_t)NROWS * DIM];   // 64 MiB
__device__ float d_xlo[(size_t)NROWS * DIM];   // 64 MiB
__device__ float d_ehi[KCODES * DIM];
__device__ float d_elo[KCODES * DIM];

// ---------------- helpers ----------------------------------------------------
__device__ __forceinline__ uint32_t smem_u32(const void* p) {
    return (uint32_t)__cvta_generic_to_shared(p);
}
__device__ __forceinline__ void cp16(uint32_t dst, const void* src) {
    asm volatile("cp.async.cg.shared.global [%0], [%1], 16;" :: "r"(dst), "l"(src));
}
__device__ __forceinline__ float tf32r(float v) {
    uint32_t r;
    asm("cvt.rna.tf32.f32 %0, %1;" : "=r"(r) : "f"(v));
    return __uint_as_float(r);
}
// order-preserving float -> u32 (ascending) and inverse
__device__ __forceinline__ uint32_t fkey(float v) {
    uint32_t u = __float_as_uint(v);
    return (u & 0x80000000u) ? ~u : (u | 0x80000000u);
}
__device__ __forceinline__ float funkey(uint32_t u) {
    return __uint_as_float((u & 0x80000000u) ? (u ^ 0x80000000u) : ~u);
}

// D += A * B  (m16n8k8, tf32 inputs as .b32 bit patterns, fp32 accum)
#define MMA_TF32(c, a, b) \
    asm volatile("mma.sync.aligned.m16n8k8.row.col.f32.tf32.tf32.f32 " \
        "{%0,%1,%2,%3}, {%4,%5,%6,%7}, {%8,%9}, {%0,%1,%2,%3};" \
        : "+f"((c)[0]), "+f"((c)[1]), "+f"((c)[2]), "+f"((c)[3]) \
        : "r"((a).x), "r"((a).y), "r"((a).z), "r"((a).w), \
          "r"((b).x), "r"((b).y))

// ---------------- smem layout of vq_mma --------------------------------------
// stage: A_hi[mt8][kt4][lane32][4f] | A_lo | B_hi[nt16][kt4][lane32][2f] | B_lo
#define OFF_AHI   0
#define OFF_ALO   16384
#define OFF_BHI   32768
#define OFF_BLO   49152
#define STG       65536
#define SM_E2     0
#define SM_BSUM   4096
#define SM_SKEY   4352       // 128 x u64 = 1024 B
#define SM_STAGE  5376
#define SMEM_MMA  (SM_STAGE + 2*STG)   // 136448 B

// ---------------- pre-pass: codebook pack + norms + zero stats ---------------
// B fragment (m16n8k8 tf32): lane holds b0=B[k=lane%4][n=lane/4], b1=B[k+4][n].
__global__ __launch_bounds__(256)
void vq_pack_e(const float* __restrict__ e) {
    const int tid = threadIdx.x, wid = tid >> 5, lane = tid & 31;
    const int nt = blockIdx.x;             // 128 ntiles of 8 codes
    const int n = nt * 8 + (lane >> 2);
    #pragma unroll
    for (int q = 0; q < 4; q++) {
        int kt = wid * 4 + q;
        int k = kt * 8 + (lane & 3);
        float v0 = e[(size_t)n * DIM + k];
        float v1 = e[(size_t)n * DIM + k + 4];
        float h0 = tf32r(v0), h1 = tf32r(v1);
        size_t o = (((size_t)nt * 32 + kt) * 32 + lane) * 2;
        *(float2*)(d_ehi + o) = make_float2(h0, h1);
        *(float2*)(d_elo + o) = make_float2(tf32r(v0 - h0), tf32r(v1 - h1));
    }
    {
        int code = nt * 8 + wid;
        float s = 0.f;
        #pragma unroll
        for (int j = 0; j < 8; j++) {
            float v = e[(size_t)code * DIM + lane + 32 * j];
            s += v * v;
        }
        #pragma unroll
        for (int o = 16; o; o >>= 1) s += __shfl_down_sync(0xffffffffu, s, o);
        if (lane == 0) { d_e2[code] = s; d_counts[code] = 0; }
    }
    if (blockIdx.x == 0 && tid == 0) d_sumd2 = 0.f;
}

// ---------------- pre-pass: x transpose + tf32 split + fragment pack ---------
// A fragment: lane holds a0=A[r=lane/4][c=lane%4], a1=A[r+8][c],
// a2=A[r][c+4], a3=A[r+8][c+4].
__global__ __launch_bounds__(256)
void vq_pack_x(const float* __restrict__ x) {
    __shared__ float sm[DIM][33];
    const int tid = threadIdx.x;
    const int b  = blockIdx.x >> 7;
    const int t0 = (blockIdx.x & 127) * 32;
    const int tx = tid & 31, ty = tid >> 5;
    const float* src = x + (size_t)b * DIM * TLEN + t0 + tx;
    #pragma unroll
    for (int dd = 0; dd < 32; dd++) {
        int d = dd * 8 + ty;
        sm[d][tx] = src[(size_t)d * TLEN];
    }
    __syncthreads();

    // row norms (8 threads per row)
    {
        const int half = tid & 7, r = tid >> 3;
        float part = 0.f;
        #pragma unroll 8
        for (int kk = 0; kk < 32; kk++) {
            float v = sm[half * 32 + kk][r];
            part += v * v;
        }
        #pragma unroll
        for (int o = 4; o; o >>= 1) part += __shfl_down_sync(0xffffffffu, part, o);
        if (half == 0) d_x2[(size_t)b * TLEN + t0 + r] = part;
    }

    // fragment packing: 2 mtiles x 32 kt x 32 lanes = 2048 float4 per array
    const int mt0 = blockIdx.x * 2;
    #pragma unroll
    for (int j = 0; j < 8; j++) {
        int i = tid + 256 * j;
        int lane = i & 31, kt = (i >> 5) & 31, mtl = i >> 10;
        int tr = mtl * 16 + (lane >> 2);
        int k0 = kt * 8 + (lane & 3);
        float v00 = sm[k0][tr],     v10 = sm[k0][tr + 8];
        float v01 = sm[k0 + 4][tr], v11 = sm[k0 + 4][tr + 8];
        float4 hv = make_float4(tf32r(v00), tf32r(v10), tf32r(v01), tf32r(v11));
        float4 lv = make_float4(tf32r(v00 - hv.x), tf32r(v10 - hv.y),
                                tf32r(v01 - hv.z), tf32r(v11 - hv.w));
        size_t o = (((size_t)(mt0 + mtl) * 32 + kt) * 32 + lane) * 4;
        *(float4*)(d_xhi + o) = hv;
        *(float4*)(d_xlo + o) = lv;
    }
}

// ---------------- stage copy (cp.async) ---------------------------------------
__device__ __forceinline__ void stage_copy(uint32_t sbase, int tid, int mt0, int it, int buf) {
    const int nc = it >> 3, kc = it & 7;
    const uint32_t stg = sbase + SM_STAGE + buf * STG;
    // A: 8 mt x 4 kt x 32 lanes, 16B each (hi + lo)
    #pragma unroll
    for (int j = 0; j < 4; j++) {
        int i = tid + 256 * j;
        int lane = i & 31, kt = (i >> 5) & 3, mt = i >> 7;
        size_t g = (((size_t)(mt0 + mt) * 32 + kc * 4 + kt) * 32 + lane) * 4;
        uint32_t d = stg + ((mt * 4 + kt) * 32 + lane) * 16;
        cp16(d + OFF_AHI, d_xhi + g);
        cp16(d + OFF_ALO, d_xlo + g);
    }
    // B: 16 nt x 4 kt x 16 lane-pairs, 16B each (hi + lo)
    #pragma unroll
    for (int j = 0; j < 4; j++) {
        int i = tid + 256 * j;
        int lp = i & 15, kt = (i >> 4) & 3, nt = i >> 6;
        size_t g = (((size_t)(nc * 16 + nt) * 32 + kc * 4 + kt) * 32 + lp * 2) * 2;
        uint32_t d = stg + ((nt * 4 + kt) * 32 + lp * 2) * 8;
        cp16(d + OFF_BHI, d_ehi + g);
        cp16(d + OFF_BLO, d_elo + g);
    }
    asm volatile("cp.async.commit_group;");
}

// ---------------- main: 3-pass split-TF32 mma.sync GEMM + argmin -------------
__global__ __launch_bounds__(256, 1)
void vq_mma() {
    extern __shared__ char smem[];
    const uint32_t sb = smem_u32(smem);
    float* e2s = (float*)smem;
    float* bsum = (float*)(smem + SM_BSUM);
    unsigned long long* skey = (unsigned long long*)(smem + SM_SKEY);
    const int tid = threadIdx.x, wid = tid >> 5, lane = tid & 31;
    const int wm = wid & 3, wn = wid >> 2;       // warp grid 4(M) x 2(N)
    const int row0 = blockIdx.x * 128;
    const int mt0  = blockIdx.x * 8;

    stage_copy(sb, tid, mt0, 0, 0);              // prefetch stage 0 ASAP
    for (int i = tid; i < KCODES; i += 256) e2s[i] = d_e2[i];
    if (tid < 128) skey[tid] = ~0ull;
    if (tid == 0) *bsum = 0.f;

    float best[4];
    int   bidx[4];
    #pragma unroll
    for (int s = 0; s < 4; s++) { best[s] = INFINITY; bidx[s] = 0; }

    float acc[2][8][4];

    for (int it = 0; it < 64; it++) {
        if (it + 1 < 64) {
            stage_copy(sb, tid, mt0, it + 1, (it + 1) & 1);
            asm volatile("cp.async.wait_group 1;");
        } else {
            asm volatile("cp.async.wait_group 0;");
        }
        __syncthreads();

        const int kc = it & 7, nc = it >> 3;
        if (kc == 0) {
            #pragma unroll
            for (int m = 0; m < 2; m++)
                #pragma unroll
                for (int n = 0; n < 8; n++)
                    #pragma unroll
                    for (int q = 0; q < 4; q++) acc[m][n][q] = 0.f;
        }

        const char* stg = smem + SM_STAGE + (it & 1) * STG;
        #pragma unroll
        for (int kt = 0; kt < 4; kt++) {
            uint4 ah[2], al[2];
            #pragma unroll
            for (int m = 0; m < 2; m++) {
                int mt = wm * 2 + m;
                ah[m] = *(const uint4*)(stg + OFF_AHI + ((mt * 4 + kt) * 32 + lane) * 16);
                al[m] = *(const uint4*)(stg + OFF_ALO + ((mt * 4 + kt) * 32 + lane) * 16);
            }
            #pragma unroll
            for (int n = 0; n < 8; n++) {
                int nt = wn * 8 + n;
                uint2 bh = *(const uint2*)(stg + OFF_BHI + ((nt * 4 + kt) * 32 + lane) * 8);
                uint2 bl = *(const uint2*)(stg + OFF_BLO + ((nt * 4 + kt) * 32 + lane) * 8);
                #pragma unroll
                for (int m = 0; m < 2; m++) {
                    MMA_TF32(acc[m][n], ah[m], bh);
                    MMA_TF32(acc[m][n], ah[m], bl);
                    MMA_TF32(acc[m][n], al[m], bh);
                }
            }
        }
        __syncthreads();

        if (kc == 7) {
            // finalize this 128-code chunk: score = ||e||^2 - 2*dot
            #pragma unroll
            for (int n = 0; n < 8; n++) {
                const int n0 = nc * 128 + wn * 64 + n * 8 + 2 * (lane & 3);
                const float e20 = e2s[n0], e21 = e2s[n0 + 1];
                #pragma unroll
                for (int m = 0; m < 2; m++) {
                    const int s0 = m * 2;
                    float sc;
                    sc = fmaf(-2.f, acc[m][n][0], e20);
                    if (sc < best[s0])   { best[s0]   = sc; bidx[s0]   = n0; }
                    sc = fmaf(-2.f, acc[m][n][1], e21);
                    if (sc < best[s0])   { best[s0]   = sc; bidx[s0]   = n0 + 1; }
                    sc = fmaf(-2.f, acc[m][n][2], e20);
                    if (sc < best[s0+1]) { best[s0+1] = sc; bidx[s0+1] = n0; }
                    sc = fmaf(-2.f, acc[m][n][3], e21);
                    if (sc < best[s0+1]) { best[s0+1] = sc; bidx[s0+1] = n0 + 1; }
                }
            }
        }
    }

    // reduce across the 4 quad lanes (same rows, disjoint cols), then across
    // the two wn warps (same rows, disjoint code halves) via shared atomicMin
    // on a packed (score,idx) key. Lower idx wins ties -> matches jnp.argmin.
    #pragma unroll
    for (int s = 0; s < 4; s++) {
        float v = best[s];
        int   ix = bidx[s];
        #pragma unroll
        for (int o = 1; o <= 2; o <<= 1) {
            float v2 = __shfl_xor_sync(0xffffffffu, v, o);
            int   i2 = __shfl_xor_sync(0xffffffffu, ix, o);
            if (v2 < v || (v2 == v && i2 < ix)) { v = v2; ix = i2; }
        }
        if ((lane & 3) == 0) {
            int lrow = wm * 32 + (s >> 1) * 16 + (s & 1) * 8 + (lane >> 2);
            unsigned long long key = ((unsigned long long)fkey(v) << 32)
                                   | (unsigned)ix;
            atomicMin(&skey[lrow], key);
        }
    }
    __syncthreads();

    if (tid < 128) {
        unsigned long long key = skey[tid];
        int   ix = (int)(key & 0xffffffffull);
        float v  = funkey((uint32_t)(key >> 32));
        int row = row0 + tid;
        d_idx[row] = ix;
        atomicAdd(&d_counts[ix], 1);
        float lsum = d_x2[row] + v;            // ||x - e||^2
        #pragma unroll
        for (int o = 16; o; o >>= 1) lsum += __shfl_down_sync(0xffffffffu, lsum, o);
        if (lane == 0) atomicAdd(bsum, lsum);
    }
    __syncthreads();
    if (tid == 0) atomicAdd(&d_sumd2, *bsum);
}

// ---------------- gather codewords, write z_q in (B, D, T) layout ------------
__global__ __launch_bounds__(256)
void vq_gather(const float* __restrict__ embed, float* __restrict__ out) {
    __shared__ float sh[32 * 257];
    __shared__ int sidx[32];
    const int tid = threadIdx.x;
    const int row0 = blockIdx.x * 32;
    const int b = row0 >> 12, t0 = row0 & (TLEN - 1);

    if (tid < 32) sidx[tid] = d_idx[row0 + tid];
    __syncthreads();
    for (int i = tid; i < 32 * DIM; i += 256) {
        int r = i >> 8, d = i & 255;
        sh[r * 257 + d] = embed[(size_t)sidx[r] * DIM + d];
    }
    __syncthreads();
    float* ob = out + (size_t)b * DIM * TLEN + t0;
    for (int i = tid; i < 32 * DIM; i += 256) {
        int tl = i & 31, d = i >> 5;
        ob[(size_t)d * TLEN + tl] = sh[tl * 257 + d];
    }
}

// ---------------- scalars: loss, kldiv_r, perplexity -------------------------
__global__ void vq_finalize(float* __restrict__ out, int out_size) {
    __shared__ float red[32];
    const int tid = threadIdx.x;   // 1024 threads
    float p = (float)d_counts[tid] * (1.0f / (float)NROWS);
    float term = p * logf(p + 1e-10f);
    #pragma unroll
    for (int off = 16; off; off >>= 1) term += __shfl_down_sync(0xffffffffu, term, off);
    if ((tid & 31) == 0) red[tid >> 5] = term;
    __syncthreads();
    if (tid < 32) {
        float v = red[tid];
        #pragma unroll
        for (int off = 16; off; off >>= 1) v += __shfl_down_sync(0xffffffffu, v, off);
        if (tid == 0) {
            float perp = expf(-v);
            float loss = 1.25f * d_sumd2 * (1.0f / (float)ZQ_ELEMS);
            float kld  = (float)(log((double)KCODES) * (double)TLEN);
            int Z = ZQ_ELEMS;
            if (Z < out_size) out[Z] = loss;
            for (int i = 0; i < BATCH; i++)
                if (Z + 1 + i < out_size) out[Z + 1 + i] = kld;
            if (Z + 17 < out_size) out[Z + 17] = perp;
        }
    }
}

// ---------------- launcher ----------------------------------------------------
extern "C" void kernel_launch(void* const* d_in, const int* in_sizes, int n_in,
                              void* d_out, int out_size) {
    const float* a0 = (const float*)d_in[0];
    const float* a1 = (const float*)d_in[1];
    const float* x;
    const float* embed;
    if (in_sizes[0] == ZQ_ELEMS) { x = a0; embed = a1; }
    else                         { x = a1; embed = a0; }
    float* out = (float*)d_out;

    cudaFuncSetAttribute(vq_mma, cudaFuncAttributeMaxDynamicSharedMemorySize, SMEM_MMA);

    vq_pack_e<<<KCODES / 8, 256>>>(embed);
    vq_pack_x<<<BATCH * (TLEN / 32), 256>>>(x);
    vq_mma<<<NROWS / 128, 256, SMEM_MMA>>>();
    vq_gather<<<NROWS / 32, 256>>>(embed, out);
    vq_finalize<<<1, KCODES>>>(out, out_size);
}

// round 12
// speedup vs baseline: 2.7582x; 1.5593x over previous
#include <cuda_runtime.h>
#include <cstdint>

#define BATCH 16
#define DIM   256
#define TLEN  4096
#define NROWS (BATCH*TLEN)         // 65536
#define KCODES 1024
#define ZQ_ELEMS (BATCH*DIM*TLEN)  // 16777216
#define MARGIN 0.25f

// ---------------- device scratch (static; no allocations allowed) ----------
__device__ float d_e2[KCODES];
__device__ int   d_counts[KCODES];
__device__ float d_sumd2;
__device__ int   d_idx[NROWS];
__device__ float d_x2[NROWS];
__device__ int   d_nflag;
__device__ int   d_flagrows[NROWS];
__device__ unsigned long long d_rkey[NROWS];
// hi parts packed in mma-fragment order (see pack kernels)
__device__ float d_xhi[(size_t)NROWS * DIM];   // 64 MiB
__device__ float d_ehi[KCODES * DIM];

// ---------------- helpers ----------------------------------------------------
__device__ __forceinline__ uint32_t smem_u32(const void* p) {
    return (uint32_t)__cvta_generic_to_shared(p);
}
__device__ __forceinline__ void cp16(uint32_t dst, const void* src) {
    asm volatile("cp.async.cg.shared.global [%0], [%1], 16;" :: "r"(dst), "l"(src));
}
__device__ __forceinline__ float tf32r(float v) {
    uint32_t r;
    asm("cvt.rna.tf32.f32 %0, %1;" : "=r"(r) : "f"(v));
    return __uint_as_float(r);
}
// order-preserving float -> u32 (ascending) and inverse
__device__ __forceinline__ uint32_t fkey(float v) {
    uint32_t u = __float_as_uint(v);
    return (u & 0x80000000u) ? ~u : (u | 0x80000000u);
}
__device__ __forceinline__ float funkey(uint32_t u) {
    return __uint_as_float((u & 0x80000000u) ? (u ^ 0x80000000u) : ~u);
}
__device__ __forceinline__ unsigned long long pkey(float v, int ix) {
    return ((unsigned long long)fkey(v) << 32) | (unsigned)ix;
}

// D += A * B  (m16n8k8, tf32 inputs as .b32 bit patterns, fp32 accum)
#define MMA_TF32(c, a, b) \
    asm volatile("mma.sync.aligned.m16n8k8.row.col.f32.tf32.tf32.f32 " \
        "{%0,%1,%2,%3}, {%4,%5,%6,%7}, {%8,%9}, {%0,%1,%2,%3};" \
        : "+f"((c)[0]), "+f"((c)[1]), "+f"((c)[2]), "+f"((c)[3]) \
        : "r"((a).x), "r"((a).y), "r"((a).z), "r"((a).w), \
          "r"((b).x), "r"((b).y))

// ---------------- smem layout of vq_mma --------------------------------------
#define OFF_AHI   0
#define OFF_BHI   16384
#define STG       32768
#define SM_E2     0
#define SM_BSUM   4096
#define SM_SKEY1  4352       // 128 x u64
#define SM_SKEY2  5376       // 128 x u64
#define SM_STAGE  6400
#define SMEM_MMA  (SM_STAGE + 2*STG)   // 71936 B

// ---------------- pre-pass: codebook pack + norms + zero stats ---------------
// B fragment (m16n8k8 tf32): lane holds b0=B[k=lane%4][n=lane/4], b1=B[k+4][n].
__global__ __launch_bounds__(256)
void vq_pack_e(const float* __restrict__ e) {
    const int tid = threadIdx.x, wid = tid >> 5, lane = tid & 31;
    const int nt = blockIdx.x;             // 128 ntiles of 8 codes
    const int n = nt * 8 + (lane >> 2);
    #pragma unroll
    for (int q = 0; q < 4; q++) {
        int kt = wid * 4 + q;
        int k = kt * 8 + (lane & 3);
        float v0 = e[(size_t)n * DIM + k];
        float v1 = e[(size_t)n * DIM + k + 4];
        size_t o = (((size_t)nt * 32 + kt) * 32 + lane) * 2;
        *(float2*)(d_ehi + o) = make_float2(tf32r(v0), tf32r(v1));
    }
    {
        int code = nt * 8 + wid;
        float s = 0.f;
        #pragma unroll
        for (int j = 0; j < 8; j++) {
            float v = e[(size_t)code * DIM + lane + 32 * j];
            s += v * v;
        }
        #pragma unroll
        for (int o = 16; o; o >>= 1) s += __shfl_down_sync(0xffffffffu, s, o);
        if (lane == 0) { d_e2[code] = s; d_counts[code] = 0; }
    }
    if (blockIdx.x == 0 && tid == 0) { d_sumd2 = 0.f; d_nflag = 0; }
}

// ---------------- pre-pass: x transpose + tf32 hi + row norms ----------------
// A fragment: lane holds a0=A[r=lane/4][c=lane%4], a1=A[r+8][c],
// a2=A[r][c+4], a3=A[r+8][c+4].
__global__ __launch_bounds__(256)
void vq_pack_x(const float* __restrict__ x) {
    __shared__ float sm[DIM][33];
    const int tid = threadIdx.x;
    const int b  = blockIdx.x >> 7;
    const int t0 = (blockIdx.x & 127) * 32;
    const int tx = tid & 31, ty = tid >> 5;
    const float* src = x + (size_t)b * DIM * TLEN + t0 + tx;
    #pragma unroll
    for (int dd = 0; dd < 32; dd++) {
        int d = dd * 8 + ty;
        sm[d][tx] = src[(size_t)d * TLEN];
    }
    __syncthreads();

    // row norms (8 threads per row)
    {
        const int half = tid & 7, r = tid >> 3;
        float part = 0.f;
        #pragma unroll 8
        for (int kk = 0; kk < 32; kk++) {
            float v = sm[half * 32 + kk][r];
            part += v * v;
        }
        #pragma unroll
        for (int o = 4; o; o >>= 1) part += __shfl_down_sync(0xffffffffu, part, o);
        if (half == 0) d_x2[(size_t)b * TLEN + t0 + r] = part;
    }

    // fragment packing: 2 mtiles x 32 kt x 32 lanes = 2048 float4
    const int mt0 = blockIdx.x * 2;
    #pragma unroll
    for (int j = 0; j < 8; j++) {
        int i = tid + 256 * j;
        int lane = i & 31, kt = (i >> 5) & 31, mtl = i >> 10;
        int tr = mtl * 16 + (lane >> 2);
        int k0 = kt * 8 + (lane & 3);
        float4 hv = make_float4(tf32r(sm[k0][tr]),     tf32r(sm[k0][tr + 8]),
                                tf32r(sm[k0 + 4][tr]), tf32r(sm[k0 + 4][tr + 8]));
        size_t o = (((size_t)(mt0 + mtl) * 32 + kt) * 32 + lane) * 4;
        *(float4*)(d_xhi + o) = hv;
    }
}

// ---------------- stage copy (cp.async, hi-only) ------------------------------
__device__ __forceinline__ void stage_copy(uint32_t sbase, int tid, int mt0, int it, int buf) {
    const int nc = it >> 3, kc = it & 7;
    const uint32_t stg = sbase + SM_STAGE + buf * STG;
    // A: 8 mt x 4 kt x 32 lanes x 16B
    #pragma unroll
    for (int j = 0; j < 4; j++) {
        int i = tid + 256 * j;
        int lane = i & 31, kt = (i >> 5) & 3, mt = i >> 7;
        size_t g = (((size_t)(mt0 + mt) * 32 + kc * 4 + kt) * 32 + lane) * 4;
        cp16(stg + OFF_AHI + ((mt * 4 + kt) * 32 + lane) * 16, d_xhi + g);
    }
    // B: 16 nt x 4 kt x 16 lane-pairs x 16B
    #pragma unroll
    for (int j = 0; j < 4; j++) {
        int i = tid + 256 * j;
        int lp = i & 15, kt = (i >> 4) & 3, nt = i >> 6;
        size_t g = (((size_t)(nc * 16 + nt) * 32 + kc * 4 + kt) * 32 + lp * 2) * 2;
        cp16(stg + OFF_BHI + ((nt * 4 + kt) * 32 + lp * 2) * 8, d_ehi + g);
    }
    asm volatile("cp.async.commit_group;");
}

// ---------------- main: 1-pass hi.hi TF32 GEMM + top-2 argmin ----------------
__global__ __launch_bounds__(256, 2)
void vq_mma() {
    extern __shared__ char smem[];
    const uint32_t sb = smem_u32(smem);
    float* e2s = (float*)smem;
    float* bsum = (float*)(smem + SM_BSUM);
    unsigned long long* skey1 = (unsigned long long*)(smem + SM_SKEY1);
    unsigned long long* skey2 = (unsigned long long*)(smem + SM_SKEY2);
    const int tid = threadIdx.x, wid = tid >> 5, lane = tid & 31;
    const int wm = wid & 3, wn = wid >> 2;       // warp grid 4(M) x 2(N)
    const int row0 = blockIdx.x * 128;
    const int mt0  = blockIdx.x * 8;

    stage_copy(sb, tid, mt0, 0, 0);              // prefetch stage 0 ASAP
    for (int i = tid; i < KCODES; i += 256) e2s[i] = d_e2[i];
    if (tid < 128) { skey1[tid] = ~0ull; skey2[tid] = ~0ull; }
    if (tid == 0) *bsum = 0.f;

    float b1[4], b2[4];
    int   i1[4], i2[4];
    #pragma unroll
    for (int s = 0; s < 4; s++) { b1[s] = INFINITY; b2[s] = INFINITY; i1[s] = 0; i2[s] = 0; }

    float acc[2][8][4];

    for (int it = 0; it < 64; it++) {
        if (it + 1 < 64) {
            stage_copy(sb, tid, mt0, it + 1, (it + 1) & 1);
            asm volatile("cp.async.wait_group 1;");
        } else {
            asm volatile("cp.async.wait_group 0;");
        }
        __syncthreads();

        const int kc = it & 7, nc = it >> 3;
        if (kc == 0) {
            #pragma unroll
            for (int m = 0; m < 2; m++)
                #pragma unroll
                for (int n = 0; n < 8; n++)
                    #pragma unroll
                    for (int q = 0; q < 4; q++) acc[m][n][q] = 0.f;
        }

        const char* stg = smem + SM_STAGE + (it & 1) * STG;
        #pragma unroll
        for (int kt = 0; kt < 4; kt++) {
            uint4 ah[2];
            #pragma unroll
            for (int m = 0; m < 2; m++) {
                int mt = wm * 2 + m;
                ah[m] = *(const uint4*)(stg + OFF_AHI + ((mt * 4 + kt) * 32 + lane) * 16);
            }
            #pragma unroll
            for (int n = 0; n < 8; n++) {
                int nt = wn * 8 + n;
                uint2 bh = *(const uint2*)(stg + OFF_BHI + ((nt * 4 + kt) * 32 + lane) * 8);
                #pragma unroll
                for (int m = 0; m < 2; m++) MMA_TF32(acc[m][n], ah[m], bh);
            }
        }
        __syncthreads();

        if (kc == 7) {
            // finalize chunk: score = ||e||^2 - 2*dot; track top-2 per slot
            #pragma unroll
            for (int n = 0; n < 8; n++) {
                const int n0 = nc * 128 + wn * 64 + n * 8 + 2 * (lane & 3);
                const float e20 = e2s[n0], e21 = e2s[n0 + 1];
                #pragma unroll
                for (int m = 0; m < 2; m++) {
                    #pragma unroll
                    for (int q = 0; q < 4; q++) {
                        const int s = m * 2 + (q >> 1);
                        const int ix = n0 + (q & 1);
                        float sc = fmaf(-2.f, acc[m][n][q], (q & 1) ? e21 : e20);
                        if (sc < b1[s]) {
                            b2[s] = b1[s]; i2[s] = i1[s];
                            b1[s] = sc;    i1[s] = ix;
                        } else if (sc < b2[s]) {
                            b2[s] = sc;    i2[s] = ix;
                        }
                    }
                }
            }
        }
    }

    // top-2 merge across the 4 quad lanes (same rows, disjoint cols), then
    // across wn warp halves via two-stage shared atomicMin on packed keys.
    #pragma unroll
    for (int s = 0; s < 4; s++) {
        unsigned long long k1 = pkey(b1[s], i1[s]);
        unsigned long long k2 = pkey(b2[s], i2[s]);
        #pragma unroll
        for (int o = 1; o <= 2; o <<= 1) {
            unsigned long long ok1 = __shfl_xor_sync(0xffffffffu, k1, o);
            unsigned long long ok2 = __shfl_xor_sync(0xffffffffu, k2, o);
            if (ok1 < k1) { k2 = (k1 < ok2) ? k1 : ok2; k1 = ok1; }
            else          { k2 = (k2 < ok1) ? k2 : ok1; }
        }
        if ((lane & 3) == 0) {
            int lrow = wm * 32 + (s >> 1) * 16 + (s & 1) * 8 + (lane >> 2);
            atomicMin(&skey1[lrow], k1);
            // stash for phase 2
            b1[s] = __uint_as_float((uint32_t)(k1 >> 32)); i1[s] = (int)(k1 & 0xffffffffull);
            b2[s] = __uint_as_float((uint32_t)(k2 >> 32)); i2[s] = (int)(k2 & 0xffffffffull);
        }
    }
    __syncthreads();
    #pragma unroll
    for (int s = 0; s < 4; s++) {
        if ((lane & 3) == 0) {
            int lrow = wm * 32 + (s >> 1) * 16 + (s & 1) * 8 + (lane >> 2);
            unsigned long long k1 = ((unsigned long long)__float_as_uint(b1[s]) << 32) | (unsigned)i1[s];
            unsigned long long k2 = ((unsigned long long)__float_as_uint(b2[s]) << 32) | (unsigned)i2[s];
            atomicMin(&skey2[lrow], k2);
            if (k1 != skey1[lrow]) atomicMin(&skey2[lrow], k1);
        }
    }
    __syncthreads();

    if (tid < 128) {
        unsigned long long k1 = skey1[tid], k2 = skey2[tid];
        float v1 = funkey((uint32_t)(k1 >> 32));
        float v2 = funkey((uint32_t)(k2 >> 32));
        int   ix = (int)(k1 & 0xffffffffull);
        const int row = row0 + tid;
        float lsum = 0.f;
        if (v2 - v1 >= MARGIN) {
            d_idx[row] = ix;
            atomicAdd(&d_counts[ix], 1);
            lsum = d_x2[row] + v1;             // ||x - e||^2 (hi approx, loss only)
        } else {
            int slot = atomicAdd(&d_nflag, 1);
            d_flagrows[slot] = row;
            d_rkey[row] = ~0ull;
            d_idx[row] = ix;                   // provisional; rescore overwrites
        }
        #pragma unroll
        for (int o = 16; o; o >>= 1) lsum += __shfl_down_sync(0xffffffffu, lsum, o);
        if (lane == 0) atomicAdd(bsum, lsum);
    }
    __syncthreads();
    if (tid == 0) atomicAdd(&d_sumd2, *bsum);
}

// ---------------- exact fp32 rescore of flagged rows -------------------------
#define RS_G 16
__global__ __launch_bounds__(256)
void vq_rescore(const float* __restrict__ x, const float* __restrict__ embed) {
    __shared__ float xs[RS_G][260];
    __shared__ unsigned long long sk[RS_G];
    const int tid = threadIdx.x;
    const int c = blockIdx.y * 256 + tid;      // this thread's code
    const int nf = d_nflag;
    const float e2v = d_e2[c];
    const float* ev = embed + (size_t)c * DIM;

    for (int g0 = blockIdx.x * RS_G; g0 < nf; g0 += gridDim.x * RS_G) {
        const int nr = min(RS_G, nf - g0);
        if (tid < RS_G) sk[tid] = ~0ull;
        for (int i = tid; i < nr * 256; i += 256) {
            int r = i >> 8, d = i & 255;
            int row = d_flagrows[g0 + r];
            xs[r][d] = x[((size_t)(row >> 12) * DIM + d) * TLEN + (row & (TLEN - 1))];
        }
        __syncthreads();

        float dots[RS_G];
        #pragma unroll
        for (int r = 0; r < RS_G; r++) dots[r] = 0.f;
        for (int d = 0; d < 256; d += 4) {
            float4 e4 = *(const float4*)(ev + d);
            #pragma unroll
            for (int r = 0; r < RS_G; r++) {
                float4 x4 = *(const float4*)&xs[r][d];
                dots[r] = fmaf(e4.x, x4.x, fmaf(e4.y, x4.y,
                          fmaf(e4.z, x4.z, fmaf(e4.w, x4.w, dots[r]))));
            }
        }
        for (int r = 0; r < nr; r++)
            atomicMin(&sk[r], pkey(fmaf(-2.f, dots[r], e2v), c));
        __syncthreads();
        if (tid < nr) atomicMin(&d_rkey[d_flagrows[g0 + tid]], sk[tid]);
        __syncthreads();
    }
}

// ---------------- fixup: commit rescored rows --------------------------------
__global__ __launch_bounds__(256)
void vq_fixup() {
    __shared__ float red[32];
    const int tid = threadIdx.x, lane = tid & 31;
    const int nf = d_nflag;
    float ls = 0.f;
    for (int i = tid; i < nf; i += 256) {
        int row = d_flagrows[i];
        unsigned long long k = d_rkey[row];
        int ix = (int)(k & 0xffffffffull);
        d_idx[row] = ix;
        atomicAdd(&d_counts[ix], 1);
        ls += d_x2[row] + funkey((uint32_t)(k >> 32));
    }
    #pragma unroll
    for (int o = 16; o; o >>= 1) ls += __shfl_down_sync(0xffffffffu, ls, o);
    if (lane == 0) red[tid >> 5] = ls;
    __syncthreads();
    if (tid < 32) {
        float v = (tid < 8) ? red[tid] : 0.f;
        #pragma unroll
        for (int o = 4; o; o >>= 1) v += __shfl_down_sync(0xffffffffu, v, o);
        if (tid == 0) atomicAdd(&d_sumd2, v);
    }
}

// ---------------- gather codewords, write z_q in (B, D, T) layout ------------
__global__ __launch_bounds__(256)
void vq_gather(const float* __restrict__ embed, float* __restrict__ out) {
    __shared__ float sh[32 * 257];
    __shared__ int sidx[32];
    const int tid = threadIdx.x;
    const int row0 = blockIdx.x * 32;
    const int b = row0 >> 12, t0 = row0 & (TLEN - 1);

    if (tid < 32) sidx[tid] = d_idx[row0 + tid];
    __syncthreads();
    for (int i = tid; i < 32 * DIM; i += 256) {
        int r = i >> 8, d = i & 255;
        sh[r * 257 + d] = embed[(size_t)sidx[r] * DIM + d];
    }
    __syncthreads();
    float* ob = out + (size_t)b * DIM * TLEN + t0;
    for (int i = tid; i < 32 * DIM; i += 256) {
        int tl = i & 31, d = i >> 5;
        ob[(size_t)d * TLEN + tl] = sh[tl * 257 + d];
    }
}

// ---------------- scalars: loss, kldiv_r, perplexity -------------------------
__global__ void vq_finalize(float* __restrict__ out, int out_size) {
    __shared__ float red[32];
    const int tid = threadIdx.x;   // 1024 threads
    float p = (float)d_counts[tid] * (1.0f / (float)NROWS);
    float term = p * logf(p + 1e-10f);
    #pragma unroll
    for (int off = 16; off; off >>= 1) term += __shfl_down_sync(0xffffffffu, term, off);
    if ((tid & 31) == 0) red[tid >> 5] = term;
    __syncthreads();
    if (tid < 32) {
        float v = red[tid];
        #pragma unroll
        for (int off = 16; off; off >>= 1) v += __shfl_down_sync(0xffffffffu, v, off);
        if (tid == 0) {
            float perp = expf(-v);
            float loss = 1.25f * d_sumd2 * (1.0f / (float)ZQ_ELEMS);
            float kld  = (float)(log((double)KCODES) * (double)TLEN);
            int Z = ZQ_ELEMS;
            if (Z < out_size) out[Z] = loss;
            for (int i = 0; i < BATCH; i++)
                if (Z + 1 + i < out_size) out[Z + 1 + i] = kld;
            if (Z + 17 < out_size) out[Z + 17] = perp;
        }
    }
}

// ---------------- launcher ----------------------------------------------------
extern "C" void kernel_launch(void* const* d_in, const int* in_sizes, int n_in,
                              void* d_out, int out_size) {
    const float* a0 = (const float*)d_in[0];
    const float* a1 = (const float*)d_in[1];
    const float* x;
    const float* embed;
    if (in_sizes[0] == ZQ_ELEMS) { x = a0; embed = a1; }
    else                         { x = a1; embed = a0; }
    float* out = (float*)d_out;

    cudaFuncSetAttribute(vq_mma, cudaFuncAttributeMaxDynamicSharedMemorySize, SMEM_MMA);

    vq_pack_e<<<KCODES / 8, 256>>>(embed);
    vq_pack_x<<<BATCH * (TLEN / 32), 256>>>(x);
    vq_mma<<<NROWS / 128, 256, SMEM_MMA>>>();
    vq_rescore<<<dim3(64, 4), 256>>>(x, embed);
    vq_fixup<<<1, 256>>>();
    vq_gather<<<NROWS / 32, 256>>>(embed, out);
    vq_finalize<<<1, KCODES>>>(out, out_size);
}

// round 13
// speedup vs baseline: 2.7878x; 1.0107x over previous
#include <cuda_runtime.h>
#include <cstdint>

#define BATCH 16
#define DIM   256
#define TLEN  4096
#define NROWS (BATCH*TLEN)         // 65536
#define KCODES 1024
#define ZQ_ELEMS (BATCH*DIM*TLEN)  // 16777216
#define MARGIN 0.25f

// ---------------- device scratch (static; no allocations allowed) ----------
__device__ float d_e2[KCODES];
__device__ int   d_counts[KCODES];
__device__ float d_sumd2;
__device__ int   d_idx[NROWS];
__device__ float d_x2[NROWS];
__device__ int   d_nflag;
__device__ int   d_flagrows[NROWS];
__device__ unsigned long long d_rkey[NROWS];
__device__ float d_xhi[(size_t)NROWS * DIM];   // 64 MiB, mma-fragment order
__device__ float d_xt [(size_t)NROWS * DIM];   // 64 MiB, exact fp32 row-major
__device__ float d_ehi[KCODES * DIM];

// ---------------- helpers ----------------------------------------------------
__device__ __forceinline__ uint32_t smem_u32(const void* p) {
    return (uint32_t)__cvta_generic_to_shared(p);
}
__device__ __forceinline__ void cp16(uint32_t dst, const void* src) {
    asm volatile("cp.async.cg.shared.global [%0], [%1], 16;" :: "r"(dst), "l"(src));
}
__device__ __forceinline__ float tf32r(float v) {
    uint32_t r;
    asm("cvt.rna.tf32.f32 %0, %1;" : "=r"(r) : "f"(v));
    return __uint_as_float(r);
}
// order-preserving float -> u32 (ascending) and inverse
__device__ __forceinline__ uint32_t fkey(float v) {
    uint32_t u = __float_as_uint(v);
    return (u & 0x80000000u) ? ~u : (u | 0x80000000u);
}
__device__ __forceinline__ float funkey(uint32_t u) {
    return __uint_as_float((u & 0x80000000u) ? (u ^ 0x80000000u) : ~u);
}
__device__ __forceinline__ unsigned long long pkey(float v, int ix) {
    return ((unsigned long long)fkey(v) << 32) | (unsigned)ix;
}

// D += A * B  (m16n8k8, tf32 inputs as .b32 bit patterns, fp32 accum)
#define MMA_TF32(c, a, b) \
    asm volatile("mma.sync.aligned.m16n8k8.row.col.f32.tf32.tf32.f32 " \
        "{%0,%1,%2,%3}, {%4,%5,%6,%7}, {%8,%9}, {%0,%1,%2,%3};" \
        : "+f"((c)[0]), "+f"((c)[1]), "+f"((c)[2]), "+f"((c)[3]) \
        : "r"((a).x), "r"((a).y), "r"((a).z), "r"((a).w), \
          "r"((b).x), "r"((b).y))

// ---------------- smem layout of vq_mma --------------------------------------
#define OFF_AHI   0
#define OFF_BHI   16384
#define STG       32768
#define SM_E2     0
#define SM_BSUM   4096
#define SM_SKEY1  4352       // 128 x u64
#define SM_SKEY2  5376       // 128 x u64
#define SM_STAGE  6400
#define SMEM_MMA  (SM_STAGE + 2*STG)   // 71936 B

// ---------------- pre-pass: codebook pack + norms + zero stats ---------------
__global__ __launch_bounds__(256)
void vq_pack_e(const float* __restrict__ e) {
    const int tid = threadIdx.x, wid = tid >> 5, lane = tid & 31;
    const int nt = blockIdx.x;             // 128 ntiles of 8 codes
    const int n = nt * 8 + (lane >> 2);
    #pragma unroll
    for (int q = 0; q < 4; q++) {
        int kt = wid * 4 + q;
        int k = kt * 8 + (lane & 3);
        float v0 = e[(size_t)n * DIM + k];
        float v1 = e[(size_t)n * DIM + k + 4];
        size_t o = (((size_t)nt * 32 + kt) * 32 + lane) * 2;
        *(float2*)(d_ehi + o) = make_float2(tf32r(v0), tf32r(v1));
    }
    {
        int code = nt * 8 + wid;
        float s = 0.f;
        #pragma unroll
        for (int j = 0; j < 8; j++) {
            float v = e[(size_t)code * DIM + lane + 32 * j];
            s += v * v;
        }
        #pragma unroll
        for (int o = 16; o; o >>= 1) s += __shfl_down_sync(0xffffffffu, s, o);
        if (lane == 0) { d_e2[code] = s; d_counts[code] = 0; }
    }
    if (blockIdx.x == 0 && tid == 0) { d_sumd2 = 0.f; d_nflag = 0; }
}

// ---------------- pre-pass: x transpose + tf32 hi + exact copy + norms -------
__global__ __launch_bounds__(256)
void vq_pack_x(const float* __restrict__ x) {
    __shared__ float sm[DIM][33];
    const int tid = threadIdx.x;
    const int b  = blockIdx.x >> 7;
    const int t0 = (blockIdx.x & 127) * 32;
    const int tx = tid & 31, ty = tid >> 5;
    const float* src = x + (size_t)b * DIM * TLEN + t0 + tx;
    #pragma unroll
    for (int dd = 0; dd < 32; dd++) {
        int d = dd * 8 + ty;
        sm[d][tx] = src[(size_t)d * TLEN];
    }
    __syncthreads();

    // row norms (8 threads per row)
    {
        const int half = tid & 7, r = tid >> 3;
        float part = 0.f;
        #pragma unroll 8
        for (int kk = 0; kk < 32; kk++) {
            float v = sm[half * 32 + kk][r];
            part += v * v;
        }
        #pragma unroll
        for (int o = 4; o; o >>= 1) part += __shfl_down_sync(0xffffffffu, part, o);
        if (half == 0) d_x2[(size_t)b * TLEN + t0 + r] = part;
    }

    // exact row-major transposed copy (for rescore; coalesced)
    {
        const size_t row0 = (size_t)b * TLEN + t0;
        #pragma unroll
        for (int j = 0; j < 32; j++) {
            int i = tid + 256 * j;
            int r = i >> 8, d = i & 255;
            d_xt[(row0 + r) * DIM + d] = sm[d][r];
        }
    }

    // fragment packing: 2 mtiles x 32 kt x 32 lanes = 2048 float4
    const int mt0 = blockIdx.x * 2;
    #pragma unroll
    for (int j = 0; j < 8; j++) {
        int i = tid + 256 * j;
        int lane = i & 31, kt = (i >> 5) & 31, mtl = i >> 10;
        int tr = mtl * 16 + (lane >> 2);
        int k0 = kt * 8 + (lane & 3);
        float4 hv = make_float4(tf32r(sm[k0][tr]),     tf32r(sm[k0][tr + 8]),
                                tf32r(sm[k0 + 4][tr]), tf32r(sm[k0 + 4][tr + 8]));
        size_t o = (((size_t)(mt0 + mtl) * 32 + kt) * 32 + lane) * 4;
        *(float4*)(d_xhi + o) = hv;
    }
}

// ---------------- stage copy (cp.async, hi-only) ------------------------------
__device__ __forceinline__ void stage_copy(uint32_t sbase, int tid, int mt0, int it, int buf) {
    const int nc = it >> 3, kc = it & 7;
    const uint32_t stg = sbase + SM_STAGE + buf * STG;
    // A: 8 mt x 4 kt x 32 lanes x 16B
    #pragma unroll
    for (int j = 0; j < 4; j++) {
        int i = tid + 256 * j;
        int lane = i & 31, kt = (i >> 5) & 3, mt = i >> 7;
        size_t g = (((size_t)(mt0 + mt) * 32 + kc * 4 + kt) * 32 + lane) * 4;
        cp16(stg + OFF_AHI + ((mt * 4 + kt) * 32 + lane) * 16, d_xhi + g);
    }
    // B: 16 nt x 4 kt x 16 lane-pairs x 16B
    #pragma unroll
    for (int j = 0; j < 4; j++) {
        int i = tid + 256 * j;
        int lp = i & 15, kt = (i >> 4) & 3, nt = i >> 6;
        size_t g = (((size_t)(nc * 16 + nt) * 32 + kc * 4 + kt) * 32 + lp * 2) * 2;
        cp16(stg + OFF_BHI + ((nt * 4 + kt) * 32 + lp * 2) * 8, d_ehi + g);
    }
    asm volatile("cp.async.commit_group;");
}

// ---------------- main: 1-pass hi.hi TF32 GEMM + top-2 argmin ----------------
__global__ __launch_bounds__(256, 2)
void vq_mma() {
    extern __shared__ char smem[];
    const uint32_t sb = smem_u32(smem);
    float* e2s = (float*)smem;
    float* bsum = (float*)(smem + SM_BSUM);
    unsigned long long* skey1 = (unsigned long long*)(smem + SM_SKEY1);
    unsigned long long* skey2 = (unsigned long long*)(smem + SM_SKEY2);
    const int tid = threadIdx.x, wid = tid >> 5, lane = tid & 31;
    const int wm = wid & 3, wn = wid >> 2;       // warp grid 4(M) x 2(N)
    const int row0 = blockIdx.x * 128;
    const int mt0  = blockIdx.x * 8;

    stage_copy(sb, tid, mt0, 0, 0);              // prefetch stage 0 ASAP
    for (int i = tid; i < KCODES; i += 256) e2s[i] = d_e2[i];
    if (tid < 128) { skey1[tid] = ~0ull; skey2[tid] = ~0ull; }
    if (tid == 0) *bsum = 0.f;

    float b1[4], b2[4];
    int   i1[4], i2[4];
    #pragma unroll
    for (int s = 0; s < 4; s++) { b1[s] = INFINITY; b2[s] = INFINITY; i1[s] = 0; i2[s] = 0; }

    float acc[2][8][4];

    for (int it = 0; it < 64; it++) {
        if (it + 1 < 64) {
            stage_copy(sb, tid, mt0, it + 1, (it + 1) & 1);
            asm volatile("cp.async.wait_group 1;");
        } else {
            asm volatile("cp.async.wait_group 0;");
        }
        __syncthreads();

        const int kc = it & 7, nc = it >> 3;
        if (kc == 0) {
            #pragma unroll
            for (int m = 0; m < 2; m++)
                #pragma unroll
                for (int n = 0; n < 8; n++)
                    #pragma unroll
                    for (int q = 0; q < 4; q++) acc[m][n][q] = 0.f;
        }

        const char* stg = smem + SM_STAGE + (it & 1) * STG;
        #pragma unroll
        for (int kt = 0; kt < 4; kt++) {
            uint4 ah[2];
            #pragma unroll
            for (int m = 0; m < 2; m++) {
                int mt = wm * 2 + m;
                ah[m] = *(const uint4*)(stg + OFF_AHI + ((mt * 4 + kt) * 32 + lane) * 16);
            }
            #pragma unroll
            for (int n = 0; n < 8; n++) {
                int nt = wn * 8 + n;
                uint2 bh = *(const uint2*)(stg + OFF_BHI + ((nt * 4 + kt) * 32 + lane) * 8);
                #pragma unroll
                for (int m = 0; m < 2; m++) MMA_TF32(acc[m][n], ah[m], bh);
            }
        }
        __syncthreads();

        if (kc == 7) {
            // finalize chunk: score = ||e||^2 - 2*dot; track top-2 per slot
            #pragma unroll
            for (int n = 0; n < 8; n++) {
                const int n0 = nc * 128 + wn * 64 + n * 8 + 2 * (lane & 3);
                const float e20 = e2s[n0], e21 = e2s[n0 + 1];
                #pragma unroll
                for (int m = 0; m < 2; m++) {
                    #pragma unroll
                    for (int q = 0; q < 4; q++) {
                        const int s = m * 2 + (q >> 1);
                        const int ix = n0 + (q & 1);
                        float sc = fmaf(-2.f, acc[m][n][q], (q & 1) ? e21 : e20);
                        if (sc < b1[s]) {
                            b2[s] = b1[s]; i2[s] = i1[s];
                            b1[s] = sc;    i1[s] = ix;
                        } else if (sc < b2[s]) {
                            b2[s] = sc;    i2[s] = ix;
                        }
                    }
                }
            }
        }
    }

    // top-2 merge across quad lanes, then across wn halves via two-stage
    // shared atomicMin on packed keys. Lower idx wins ties (jnp.argmin).
    #pragma unroll
    for (int s = 0; s < 4; s++) {
        unsigned long long k1 = pkey(b1[s], i1[s]);
        unsigned long long k2 = pkey(b2[s], i2[s]);
        #pragma unroll
        for (int o = 1; o <= 2; o <<= 1) {
            unsigned long long ok1 = __shfl_xor_sync(0xffffffffu, k1, o);
            unsigned long long ok2 = __shfl_xor_sync(0xffffffffu, k2, o);
            if (ok1 < k1) { k2 = (k1 < ok2) ? k1 : ok2; k1 = ok1; }
            else          { k2 = (k2 < ok1) ? k2 : ok1; }
        }
        if ((lane & 3) == 0) {
            int lrow = wm * 32 + (s >> 1) * 16 + (s & 1) * 8 + (lane >> 2);
            atomicMin(&skey1[lrow], k1);
            b1[s] = __uint_as_float((uint32_t)(k1 >> 32)); i1[s] = (int)(k1 & 0xffffffffull);
            b2[s] = __uint_as_float((uint32_t)(k2 >> 32)); i2[s] = (int)(k2 & 0xffffffffull);
        }
    }
    __syncthreads();
    #pragma unroll
    for (int s = 0; s < 4; s++) {
        if ((lane & 3) == 0) {
            int lrow = wm * 32 + (s >> 1) * 16 + (s & 1) * 8 + (lane >> 2);
            unsigned long long k1 = ((unsigned long long)__float_as_uint(b1[s]) << 32) | (unsigned)i1[s];
            unsigned long long k2 = ((unsigned long long)__float_as_uint(b2[s]) << 32) | (unsigned)i2[s];
            atomicMin(&skey2[lrow], k2);
            if (k1 != skey1[lrow]) atomicMin(&skey2[lrow], k1);
        }
    }
    __syncthreads();

    if (tid < 128) {
        unsigned long long k1 = skey1[tid], k2 = skey2[tid];
        float v1 = funkey((uint32_t)(k1 >> 32));
        float v2 = funkey((uint32_t)(k2 >> 32));
        int   ix = (int)(k1 & 0xffffffffull);
        const int row = row0 + tid;
        float lsum = 0.f;
        if (v2 - v1 >= MARGIN) {
            d_idx[row] = ix;
            atomicAdd(&d_counts[ix], 1);
            lsum = d_x2[row] + v1;             // ||x - e||^2 (hi approx, loss only)
        } else {
            int slot = atomicAdd(&d_nflag, 1);
            d_flagrows[slot] = row;
            d_rkey[row] = ~0ull;
            d_idx[row] = ix;                   // provisional; rescore overwrites
        }
        #pragma unroll
        for (int o = 16; o; o >>= 1) lsum += __shfl_down_sync(0xffffffffu, lsum, o);
        if (lane == 0) atomicAdd(bsum, lsum);
    }
    __syncthreads();
    if (tid == 0) atomicAdd(&d_sumd2, *bsum);
}

// ---------------- exact fp32 rescore of flagged rows (coalesced d_xt) --------
#define RS_G 16
__global__ __launch_bounds__(256)
void vq_rescore(const float* __restrict__ embed) {
    __shared__ float xs[RS_G][260];
    __shared__ unsigned long long sk[RS_G];
    const int tid = threadIdx.x;
    const int c = blockIdx.y * 256 + tid;      // this thread's code
    const int nf = d_nflag;
    const float e2v = d_e2[c];
    const float* ev = embed + (size_t)c * DIM;

    for (int g0 = blockIdx.x * RS_G; g0 < nf; g0 += gridDim.x * RS_G) {
        const int nr = min(RS_G, nf - g0);
        if (tid < RS_G) sk[tid] = ~0ull;
        for (int i = tid; i < nr * 64; i += 256) {
            int r = i >> 6, q = i & 63;
            const float4* src = (const float4*)(d_xt + (size_t)d_flagrows[g0 + r] * DIM);
            *(float4*)&xs[r][q * 4] = src[q];
        }
        __syncthreads();

        float dots[RS_G];
        #pragma unroll
        for (int r = 0; r < RS_G; r++) dots[r] = 0.f;
        for (int d = 0; d < 256; d += 4) {
            float4 e4 = *(const float4*)(ev + d);
            #pragma unroll
            for (int r = 0; r < RS_G; r++) {
                float4 x4 = *(const float4*)&xs[r][d];
                dots[r] = fmaf(e4.x, x4.x, fmaf(e4.y, x4.y,
                          fmaf(e4.z, x4.z, fmaf(e4.w, x4.w, dots[r]))));
            }
        }
        for (int r = 0; r < nr; r++)
            atomicMin(&sk[r], pkey(fmaf(-2.f, dots[r], e2v), c));
        __syncthreads();
        if (tid < nr) atomicMin(&d_rkey[d_flagrows[g0 + tid]], sk[tid]);
        __syncthreads();
    }
}

// ---------------- fixup: commit rescored rows --------------------------------
__global__ __launch_bounds__(256)
void vq_fixup() {
    __shared__ float red[32];
    const int tid = threadIdx.x, lane = tid & 31;
    const int nf = d_nflag;
    float ls = 0.f;
    for (int i = tid; i < nf; i += 256) {
        int row = d_flagrows[i];
        unsigned long long k = d_rkey[row];
        int ix = (int)(k & 0xffffffffull);
        d_idx[row] = ix;
        atomicAdd(&d_counts[ix], 1);
        ls += d_x2[row] + funkey((uint32_t)(k >> 32));
    }
    #pragma unroll
    for (int o = 16; o; o >>= 1) ls += __shfl_down_sync(0xffffffffu, ls, o);
    if (lane == 0) red[tid >> 5] = ls;
    __syncthreads();
    if (tid < 32) {
        float v = (tid < 8) ? red[tid] : 0.f;
        #pragma unroll
        for (int o = 4; o; o >>= 1) v += __shfl_down_sync(0xffffffffu, v, o);
        if (tid == 0) atomicAdd(&d_sumd2, v);
    }
}

// ---------------- gather codewords, write z_q in (B, D, T) layout ------------
__global__ __launch_bounds__(256)
void vq_gather(const float* __restrict__ embed, float* __restrict__ out) {
    __shared__ float sh[DIM * 33];             // [d][t] layout, padded
    __shared__ int sidx[32];
    const int tid = threadIdx.x;
    const int row0 = blockIdx.x * 32;
    const int b = row0 >> 12, t0 = row0 & (TLEN - 1);

    if (tid < 32) sidx[tid] = d_idx[row0 + tid];
    __syncthreads();
    #pragma unroll
    for (int j = 0; j < 32; j++) {
        int i = tid + 256 * j;
        int r = i >> 8, d = i & 255;
        sh[d * 33 + r] = embed[(size_t)sidx[r] * DIM + d];
    }
    __syncthreads();
    float* ob = out + (size_t)b * DIM * TLEN + t0;
    #pragma unroll
    for (int j = 0; j < 8; j++) {
        int i = tid + 256 * j;
        int tl4 = (i & 7) * 4, d = i >> 3;
        float4 v = make_float4(sh[d * 33 + tl4],     sh[d * 33 + tl4 + 1],
                               sh[d * 33 + tl4 + 2], sh[d * 33 + tl4 + 3]);
        *(float4*)(ob + (size_t)d * TLEN + tl4) = v;
    }
}

// ---------------- scalars: loss, kldiv_r, perplexity -------------------------
__global__ void vq_finalize(float* __restrict__ out, int out_size) {
    __shared__ float red[32];
    const int tid = threadIdx.x;   // 1024 threads
    float p = (float)d_counts[tid] * (1.0f / (float)NROWS);
    float term = p * logf(p + 1e-10f);
    #pragma unroll
    for (int off = 16; off; off >>= 1) term += __shfl_down_sync(0xffffffffu, term, off);
    if ((tid & 31) == 0) red[tid >> 5] = term;
    __syncthreads();
    if (tid < 32) {
        float v = red[tid];
        #pragma unroll
        for (int off = 16; off; off >>= 1) v += __shfl_down_sync(0xffffffffu, v, off);
        if (tid == 0) {
            float perp = expf(-v);
            float loss = 1.25f * d_sumd2 * (1.0f / (float)ZQ_ELEMS);
            float kld  = (float)(log((double)KCODES) * (double)TLEN);
            int Z = ZQ_ELEMS;
            if (Z < out_size) out[Z] = loss;
            for (int i = 0; i < BATCH; i++)
                if (Z + 1 + i < out_size) out[Z + 1 + i] = kld;
            if (Z + 17 < out_size) out[Z + 17] = perp;
        }
    }
}

// ---------------- launcher ----------------------------------------------------
extern "C" void kernel_launch(void* const* d_in, const int* in_sizes, int n_in,
                              void* d_out, int out_size) {
    const float* a0 = (const float*)d_in[0];
    const float* a1 = (const float*)d_in[1];
    const float* x;
    const float* embed;
    if (in_sizes[0] == ZQ_ELEMS) { x = a0; embed = a1; }
    else                         { x = a1; embed = a0; }
    float* out = (float*)d_out;

    cudaFuncSetAttribute(vq_mma, cudaFuncAttributeMaxDynamicSharedMemorySize, SMEM_MMA);

    vq_pack_e<<<KCODES / 8, 256>>>(embed);
    vq_pack_x<<<BATCH * (TLEN / 32), 256>>>(x);
    vq_mma<<<NROWS / 128, 256, SMEM_MMA>>>();
    vq_rescore<<<dim3(64, 4), 256>>>(embed);
    vq_fixup<<<1, 256>>>();
    vq_gather<<<NROWS / 32, 256>>>(embed, out);
    vq_finalize<<<1, KCODES>>>(out, out_size);
}

// round 16
// speedup vs baseline: 2.8316x; 1.0157x over previous
#include <cuda_runtime.h>
#include <cstdint>

#define BATCH 16
#define DIM   256
#define TLEN  4096
#define NROWS (BATCH*TLEN)         // 65536
#define KCODES 1024
#define ZQ_ELEMS (BATCH*DIM*TLEN)  // 16777216
#define MARGIN 0.25f

// ---------------- device scratch (static; no allocations allowed) ----------
__device__ float d_e2[KCODES];
__device__ int   d_counts[KCODES];
__device__ float d_sumd2;
__device__ int   d_idx[NROWS];
__device__ float d_x2[NROWS];
__device__ int   d_nflag;
__device__ int   d_flagrows[NROWS];
__device__ unsigned long long d_rkey[NROWS];
__device__ float d_xhi[(size_t)NROWS * DIM];   // 64 MiB, mma-fragment order
__device__ float d_xt [(size_t)NROWS * DIM];   // 64 MiB, exact fp32 row-major
__device__ float d_ehi[KCODES * DIM];

// ---------------- helpers ----------------------------------------------------
__device__ __forceinline__ uint32_t smem_u32(const void* p) {
    return (uint32_t)__cvta_generic_to_shared(p);
}
__device__ __forceinline__ void cp16(uint32_t dst, const void* src) {
    asm volatile("cp.async.cg.shared.global [%0], [%1], 16;" :: "r"(dst), "l"(src));
}
__device__ __forceinline__ float tf32r(float v) {
    uint32_t r;
    asm("cvt.rna.tf32.f32 %0, %1;" : "=r"(r) : "f"(v));
    return __uint_as_float(r);
}
// order-preserving float -> u32 (ascending) and inverse
__device__ __forceinline__ uint32_t fkey(float v) {
    uint32_t u = __float_as_uint(v);
    return (u & 0x80000000u) ? ~u : (u | 0x80000000u);
}
__device__ __forceinline__ float funkey(uint32_t u) {
    return __uint_as_float((u & 0x80000000u) ? (u ^ 0x80000000u) : ~u);
}
__device__ __forceinline__ unsigned long long pkey(float v, int ix) {
    return ((unsigned long long)fkey(v) << 32) | (unsigned)ix;
}

// D += A * B  (m16n8k8, tf32 inputs as .b32 bit patterns, fp32 accum)
#define MMA_TF32(c, a, b) \
    asm volatile("mma.sync.aligned.m16n8k8.row.col.f32.tf32.tf32.f32 " \
        "{%0,%1,%2,%3}, {%4,%5,%6,%7}, {%8,%9}, {%0,%1,%2,%3};" \
        : "+f"((c)[0]), "+f"((c)[1]), "+f"((c)[2]), "+f"((c)[3]) \
        : "r"((a).x), "r"((a).y), "r"((a).z), "r"((a).w), \
          "r"((b).x), "r"((b).y))

// ---------------- smem layout of vq_mma --------------------------------------
#define OFF_AHI   0
#define OFF_BHI   16384
#define STG       32768
#define SM_E2     0
#define SM_BSUM   4096
#define SM_SKEY1  4352       // 128 x u64
#define SM_SKEY2  5376       // 128 x u64
#define SM_STAGE  6400
#define SMEM_MMA  (SM_STAGE + 2*STG)   // 71936 B

// ---------------- pre-pass: codebook pack + norms + zero stats ---------------
__global__ __launch_bounds__(256)
void vq_pack_e(const float* __restrict__ e) {
    const int tid = threadIdx.x, wid = tid >> 5, lane = tid & 31;
    const int nt = blockIdx.x;             // 128 ntiles of 8 codes
    const int n = nt * 8 + (lane >> 2);
    #pragma unroll
    for (int q = 0; q < 4; q++) {
        int kt = wid * 4 + q;
        int k = kt * 8 + (lane & 3);
        float v0 = e[(size_t)n * DIM + k];
        float v1 = e[(size_t)n * DIM + k + 4];
        size_t o = (((size_t)nt * 32 + kt) * 32 + lane) * 2;
        *(float2*)(d_ehi + o) = make_float2(tf32r(v0), tf32r(v1));
    }
    {
        int code = nt * 8 + wid;
        float s = 0.f;
        #pragma unroll
        for (int j = 0; j < 8; j++) {
            float v = e[(size_t)code * DIM + lane + 32 * j];
            s += v * v;
        }
        #pragma unroll
        for (int o = 16; o; o >>= 1) s += __shfl_down_sync(0xffffffffu, s, o);
        if (lane == 0) { d_e2[code] = s; d_counts[code] = 0; }
    }
    if (blockIdx.x == 0 && tid == 0) { d_sumd2 = 0.f; d_nflag = 0; }
}

// ---------------- pre-pass: x transpose + tf32 hi + exact copy + norms -------
__global__ __launch_bounds__(256)
void vq_pack_x(const float* __restrict__ x) {
    __shared__ float sm[DIM][33];
    const int tid = threadIdx.x;
    const int b  = blockIdx.x >> 7;
    const int t0 = (blockIdx.x & 127) * 32;
    const int tx = tid & 31, ty = tid >> 5;
    const float* src = x + (size_t)b * DIM * TLEN + t0 + tx;
    #pragma unroll
    for (int dd = 0; dd < 32; dd++) {
        int d = dd * 8 + ty;
        sm[d][tx] = src[(size_t)d * TLEN];
    }
    __syncthreads();

    // row norms (8 threads per row)
    {
        const int half = tid & 7, r = tid >> 3;
        float part = 0.f;
        #pragma unroll 8
        for (int kk = 0; kk < 32; kk++) {
            float v = sm[half * 32 + kk][r];
            part += v * v;
        }
        #pragma unroll
        for (int o = 4; o; o >>= 1) part += __shfl_down_sync(0xffffffffu, part, o);
        if (half == 0) d_x2[(size_t)b * TLEN + t0 + r] = part;
    }

    // exact row-major transposed copy (for rescore; coalesced)
    {
        const size_t row0 = (size_t)b * TLEN + t0;
        #pragma unroll
        for (int j = 0; j < 32; j++) {
            int i = tid + 256 * j;
            int r = i >> 8, d = i & 255;
            d_xt[(row0 + r) * DIM + d] = sm[d][r];
        }
    }

    // fragment packing: 2 mtiles x 32 kt x 32 lanes = 2048 float4
    const int mt0 = blockIdx.x * 2;
    #pragma unroll
    for (int j = 0; j < 8; j++) {
        int i = tid + 256 * j;
        int lane = i & 31, kt = (i >> 5) & 31, mtl = i >> 10;
        int tr = mtl * 16 + (lane >> 2);
        int k0 = kt * 8 + (lane & 3);
        float4 hv = make_float4(tf32r(sm[k0][tr]),     tf32r(sm[k0][tr + 8]),
                                tf32r(sm[k0 + 4][tr]), tf32r(sm[k0 + 4][tr + 8]));
        size_t o = (((size_t)(mt0 + mtl) * 32 + kt) * 32 + lane) * 4;
        *(float4*)(d_xhi + o) = hv;
    }
}

// ---------------- stage copy (cp.async, hi-only) ------------------------------
__device__ __forceinline__ void stage_copy(uint32_t sbase, int tid, int mt0, int it, int buf) {
    const int nc = it >> 3, kc = it & 7;
    const uint32_t stg = sbase + SM_STAGE + buf * STG;
    // A: 8 mt x 4 kt x 32 lanes x 16B
    #pragma unroll
    for (int j = 0; j < 4; j++) {
        int i = tid + 256 * j;
        int lane = i & 31, kt = (i >> 5) & 3, mt = i >> 7;
        size_t g = (((size_t)(mt0 + mt) * 32 + kc * 4 + kt) * 32 + lane) * 4;
        cp16(stg + OFF_AHI + ((mt * 4 + kt) * 32 + lane) * 16, d_xhi + g);
    }
    // B: 16 nt x 4 kt x 16 lane-pairs x 16B
    #pragma unroll
    for (int j = 0; j < 4; j++) {
        int i = tid + 256 * j;
        int lp = i & 15, kt = (i >> 4) & 3, nt = i >> 6;
        size_t g = (((size_t)(nc * 16 + nt) * 32 + kc * 4 + kt) * 32 + lp * 2) * 2;
        cp16(stg + OFF_BHI + ((nt * 4 + kt) * 32 + lp * 2) * 8, d_ehi + g);
    }
    asm volatile("cp.async.commit_group;");
}

// ---------------- main: 1-pass hi.hi TF32 GEMM + top-2 argmin ----------------
__global__ __launch_bounds__(256, 2)
void vq_mma() {
    extern __shared__ char smem[];
    const uint32_t sb = smem_u32(smem);
    float* e2s = (float*)smem;
    float* bsum = (float*)(smem + SM_BSUM);
    unsigned long long* skey1 = (unsigned long long*)(smem + SM_SKEY1);
    unsigned long long* skey2 = (unsigned long long*)(smem + SM_SKEY2);
    const int tid = threadIdx.x, wid = tid >> 5, lane = tid & 31;
    const int wm = wid & 3, wn = wid >> 2;       // warp grid 4(M) x 2(N)
    const int row0 = blockIdx.x * 128;
    const int mt0  = blockIdx.x * 8;

    stage_copy(sb, tid, mt0, 0, 0);              // prefetch stage 0 ASAP
    for (int i = tid; i < KCODES; i += 256) e2s[i] = d_e2[i];
    if (tid < 128) { skey1[tid] = ~0ull; skey2[tid] = ~0ull; }
    if (tid == 0) *bsum = 0.f;

    float b1[4], b2[4];
    int   i1[4], i2[4];
    #pragma unroll
    for (int s = 0; s < 4; s++) { b1[s] = INFINITY; b2[s] = INFINITY; i1[s] = 0; i2[s] = 0; }

    float acc[2][8][4];

    for (int it = 0; it < 64; it++) {
        if (it + 1 < 64) {
            stage_copy(sb, tid, mt0, it + 1, (it + 1) & 1);
            asm volatile("cp.async.wait_group 1;");
        } else {
            asm volatile("cp.async.wait_group 0;");
        }
        __syncthreads();

        const int kc = it & 7, nc = it >> 3;
        if (kc == 0) {
            #pragma unroll
            for (int m = 0; m < 2; m++)
                #pragma unroll
                for (int n = 0; n < 8; n++)
                    #pragma unroll
                    for (int q = 0; q < 4; q++) acc[m][n][q] = 0.f;
        }

        const char* stg = smem + SM_STAGE + (it & 1) * STG;
        #pragma unroll
        for (int kt = 0; kt < 4; kt++) {
            uint4 ah[2];
            #pragma unroll
            for (int m = 0; m < 2; m++) {
                int mt = wm * 2 + m;
                ah[m] = *(const uint4*)(stg + OFF_AHI + ((mt * 4 + kt) * 32 + lane) * 16);
            }
            #pragma unroll
            for (int n = 0; n < 8; n++) {
                int nt = wn * 8 + n;
                uint2 bh = *(const uint2*)(stg + OFF_BHI + ((nt * 4 + kt) * 32 + lane) * 8);
                #pragma unroll
                for (int m = 0; m < 2; m++) MMA_TF32(acc[m][n], ah[m], bh);
            }
        }
        __syncthreads();

        if (kc == 7) {
            // finalize chunk: score = ||e||^2 - 2*dot; track top-2 per slot
            #pragma unroll
            for (int n = 0; n < 8; n++) {
                const int n0 = nc * 128 + wn * 64 + n * 8 + 2 * (lane & 3);
                const float e20 = e2s[n0], e21 = e2s[n0 + 1];
                #pragma unroll
                for (int m = 0; m < 2; m++) {
                    #pragma unroll
                    for (int q = 0; q < 4; q++) {
                        const int s = m * 2 + (q >> 1);
                        const int ix = n0 + (q & 1);
                        float sc = fmaf(-2.f, acc[m][n][q], (q & 1) ? e21 : e20);
                        if (sc < b1[s]) {
                            b2[s] = b1[s]; i2[s] = i1[s];
                            b1[s] = sc;    i1[s] = ix;
                        } else if (sc < b2[s]) {
                            b2[s] = sc;    i2[s] = ix;
                        }
                    }
                }
            }
        }
    }

    // top-2 merge across quad lanes, then across wn halves via two-stage
    // shared atomicMin on packed keys. Lower idx wins ties (jnp.argmin).
    #pragma unroll
    for (int s = 0; s < 4; s++) {
        unsigned long long k1 = pkey(b1[s], i1[s]);
        unsigned long long k2 = pkey(b2[s], i2[s]);
        #pragma unroll
        for (int o = 1; o <= 2; o <<= 1) {
            unsigned long long ok1 = __shfl_xor_sync(0xffffffffu, k1, o);
            unsigned long long ok2 = __shfl_xor_sync(0xffffffffu, k2, o);
            if (ok1 < k1) { k2 = (k1 < ok2) ? k1 : ok2; k1 = ok1; }
            else          { k2 = (k2 < ok1) ? k2 : ok1; }
        }
        if ((lane & 3) == 0) {
            int lrow = wm * 32 + (s >> 1) * 16 + (s & 1) * 8 + (lane >> 2);
            atomicMin(&skey1[lrow], k1);
            b1[s] = __uint_as_float((uint32_t)(k1 >> 32)); i1[s] = (int)(k1 & 0xffffffffull);
            b2[s] = __uint_as_float((uint32_t)(k2 >> 32)); i2[s] = (int)(k2 & 0xffffffffull);
        }
    }
    __syncthreads();
    #pragma unroll
    for (int s = 0; s < 4; s++) {
        if ((lane & 3) == 0) {
            int lrow = wm * 32 + (s >> 1) * 16 + (s & 1) * 8 + (lane >> 2);
            unsigned long long k1 = ((unsigned long long)__float_as_uint(b1[s]) << 32) | (unsigned)i1[s];
            unsigned long long k2 = ((unsigned long long)__float_as_uint(b2[s]) << 32) | (unsigned)i2[s];
            atomicMin(&skey2[lrow], k2);
            if (k1 != skey1[lrow]) atomicMin(&skey2[lrow], k1);
        }
    }
    __syncthreads();

    if (tid < 128) {
        unsigned long long k1 = skey1[tid], k2 = skey2[tid];
        float v1 = funkey((uint32_t)(k1 >> 32));
        float v2 = funkey((uint32_t)(k2 >> 32));
        int   ix = (int)(k1 & 0xffffffffull);
        const int row = row0 + tid;
        float lsum = 0.f;
        if (v2 - v1 >= MARGIN) {
            d_idx[row] = ix;
            atomicAdd(&d_counts[ix], 1);
            lsum = d_x2[row] + v1;             // ||x - e||^2 (hi approx, loss only)
        } else {
            int slot = atomicAdd(&d_nflag, 1);
            d_flagrows[slot] = row;
            d_rkey[row] = ~0ull;
            d_idx[row] = ix;                   // provisional; rescore overwrites
        }
        #pragma unroll
        for (int o = 16; o; o >>= 1) lsum += __shfl_down_sync(0xffffffffu, lsum, o);
        if (lane == 0) atomicAdd(bsum, lsum);
    }
    __syncthreads();
    if (tid == 0) atomicAdd(&d_sumd2, *bsum);
}

// ---------------- exact fp32 rescore, GEMM-tiled ------------------------------
// grid (96, 16): y-block owns 64 codes (staged once in smem), x strides over
// 16-row flag groups. thread = (code cl=tid>>2, rows rg+4i, rg=tid&3).
#define RS_G 16
#define RS_PITCH 260
#define RS_SMEM ((64*RS_PITCH + RS_G*RS_PITCH)*4 + 128)   // 83328 B

__global__ __launch_bounds__(256)
void vq_rescore(const float* __restrict__ embed) {
    extern __shared__ float rsm[];
    float* es = rsm;                           // [64][260]
    float* xs = rsm + 64 * RS_PITCH;           // [16][260]
    unsigned long long* sk = (unsigned long long*)(rsm + (64 + RS_G) * RS_PITCH);
    const int nf = d_nflag;
    if ((int)blockIdx.x * RS_G >= nf) return;
    const int tid = threadIdx.x, lane = tid & 31;
    const int c0 = blockIdx.y * 64;
    const int cl = tid >> 2;                   // local code 0..63
    const int rg = tid & 3;                    // row phase
    const int c  = c0 + cl;
    const float e2v = d_e2[c];
    const uint32_t sb = smem_u32(rsm);

    // stage embed chunk once (64 codes x 256 dims), coalesced cp.async
    #pragma unroll
    for (int j = 0; j < 16; j++) {
        int i = tid + 256 * j;
        int row = i >> 6, q = i & 63;
        cp16(sb + (row * RS_PITCH + q * 4) * 4,
             embed + (size_t)(c0 + row) * DIM + q * 4);
    }
    asm volatile("cp.async.commit_group;");

    for (int g0 = blockIdx.x * RS_G; g0 < nf; g0 += gridDim.x * RS_G) {
        const int nr = min(RS_G, nf - g0);
        if (tid < RS_G) sk[tid] = ~0ull;
        for (int i = tid; i < nr * 64; i += 256) {
            int r = i >> 6, q = i & 63;
            cp16(sb + ((64 + r) * RS_PITCH + q * 4) * 4,
                 d_xt + (size_t)d_flagrows[g0 + r] * DIM + q * 4);
        }
        asm volatile("cp.async.commit_group;");
        asm volatile("cp.async.wait_group 0;");
        __syncthreads();

        float dots[4] = {0.f, 0.f, 0.f, 0.f};
        #pragma unroll 8
        for (int d = 0; d < 256; d += 4) {
            float4 e4 = *(const float4*)&es[cl * RS_PITCH + d];
            #pragma unroll
            for (int i = 0; i < 4; i++) {
                float4 x4 = *(const float4*)&xs[(rg + 4 * i) * RS_PITCH + d];
                dots[i] = fmaf(e4.x, x4.x, fmaf(e4.y, x4.y,
                          fmaf(e4.z, x4.z, fmaf(e4.w, x4.w, dots[i]))));
            }
        }

        // reduce min over the 8 codes in each warp, then across warps via smem
        #pragma unroll
        for (int i = 0; i < 4; i++) {
            unsigned long long k = pkey(fmaf(-2.f, dots[i], e2v), c);
            #pragma unroll
            for (int o = 4; o <= 16; o <<= 1) {
                unsigned long long ok = __shfl_xor_sync(0xffffffffu, k, o);
                if (ok < k) k = ok;
            }
            if (lane < 4) atomicMin(&sk[lane + 4 * i], k);
        }
        __syncthreads();
        if (tid < nr) atomicMin(&d_rkey[d_flagrows[g0 + tid]], sk[tid]);
        __syncthreads();
    }
}

// ---------------- fixup: commit rescored rows --------------------------------
__global__ __launch_bounds__(256)
void vq_fixup() {
    __shared__ float red[32];
    const int tid = threadIdx.x, lane = tid & 31;
    const int nf = d_nflag;
    float ls = 0.f;
    for (int i = tid; i < nf; i += 256) {
        int row = d_flagrows[i];
        unsigned long long k = d_rkey[row];
        int ix = (int)(k & 0xffffffffull);
        d_idx[row] = ix;
        atomicAdd(&d_counts[ix], 1);
        ls += d_x2[row] + funkey((uint32_t)(k >> 32));
    }
    #pragma unroll
    for (int o = 16; o; o >>= 1) ls += __shfl_down_sync(0xffffffffu, ls, o);
    if (lane == 0) red[tid >> 5] = ls;
    __syncthreads();
    if (tid < 32) {
        float v = (tid < 8) ? red[tid] : 0.f;
        #pragma unroll
        for (int o = 4; o; o >>= 1) v += __shfl_down_sync(0xffffffffu, v, o);
        if (tid == 0) atomicAdd(&d_sumd2, v);
    }
}

// ---------------- gather codewords, write z_q in (B, D, T) layout ------------
__global__ __launch_bounds__(256)
void vq_gather(const float* __restrict__ embed, float* __restrict__ out) {
    __shared__ float sh[DIM * 33];             // [d][t] layout, padded
    __shared__ int sidx[32];
    const int tid = threadIdx.x;
    const int row0 = blockIdx.x * 32;
    const int b = row0 >> 12, t0 = row0 & (TLEN - 1);

    if (tid < 32) sidx[tid] = d_idx[row0 + tid];
    __syncthreads();
    #pragma unroll
    for (int j = 0; j < 32; j++) {
        int i = tid + 256 * j;
        int r = i >> 8, d = i & 255;
        sh[d * 33 + r] = embed[(size_t)sidx[r] * DIM + d];
    }
    __syncthreads();
    float* ob = out + (size_t)b * DIM * TLEN + t0;
    #pragma unroll
    for (int j = 0; j < 8; j++) {
        int i = tid + 256 * j;
        int tl4 = (i & 7) * 4, d = i >> 3;
        float4 v = make_float4(sh[d * 33 + tl4],     sh[d * 33 + tl4 + 1],
                               sh[d * 33 + tl4 + 2], sh[d * 33 + tl4 + 3]);
        *(float4*)(ob + (size_t)d * TLEN + tl4) = v;
    }
}

// ---------------- scalars: loss, kldiv_r, perplexity -------------------------
__global__ void vq_finalize(float* __restrict__ out, int out_size) {
    __shared__ float red[32];
    const int tid = threadIdx.x;   // 1024 threads
    float p = (float)d_counts[tid] * (1.0f / (float)NROWS);
    float term = p * logf(p + 1e-10f);
    #pragma unroll
    for (int off = 16; off; off >>= 1) term += __shfl_down_sync(0xffffffffu, term, off);
    if ((tid & 31) == 0) red[tid >> 5] = term;
    __syncthreads();
    if (tid < 32) {
        float v = red[tid];
        #pragma unroll
        for (int off = 16; off; off >>= 1) v += __shfl_down_sync(0xffffffffu, v, off);
        if (tid == 0) {
            float perp = expf(-v);
            float loss = 1.25f * d_sumd2 * (1.0f / (float)ZQ_ELEMS);
            float kld  = (float)(log((double)KCODES) * (double)TLEN);
            int Z = ZQ_ELEMS;
            if (Z < out_size) out[Z] = loss;
            for (int i = 0; i < BATCH; i++)
                if (Z + 1 + i < out_size) out[Z + 1 + i] = kld;
            if (Z + 17 < out_size) out[Z + 17] = perp;
        }
    }
}

// ---------------- launcher ----------------------------------------------------
extern "C" void kernel_launch(void* const* d_in, const int* in_sizes, int n_in,
                              void* d_out, int out_size) {
    const float* a0 = (const float*)d_in[0];
    const float* a1 = (const float*)d_in[1];
    const float* x;
    const float* embed;
    if (in_sizes[0] == ZQ_ELEMS) { x = a0; embed = a1; }
    else                         { x = a1; embed = a0; }
    float* out = (float*)d_out;

    cudaFuncSetAttribute(vq_mma, cudaFuncAttributeMaxDynamicSharedMemorySize, SMEM_MMA);
    cudaFuncSetAttribute(vq_rescore, cudaFuncAttributeMaxDynamicSharedMemorySize, RS_SMEM);

    vq_pack_e<<<KCODES / 8, 256>>>(embed);
    vq_pack_x<<<BATCH * (TLEN / 32), 256>>>(x);
    vq_mma<<<NROWS / 128, 256, SMEM_MMA>>>();
    vq_rescore<<<dim3(96, 16), 256, RS_SMEM>>>(embed);
    vq_fixup<<<1, 256>>>();
    vq_gather<<<NROWS / 32, 256>>>(embed, out);
    vq_finalize<<<1, KCODES>>>(out, out_size);
}

// round 17
// speedup vs baseline: 2.8340x; 1.0008x over previous
#include <cuda_runtime.h>
#include <cstdint>

#define BATCH 16
#define DIM   256
#define TLEN  4096
#define NROWS (BATCH*TLEN)         // 65536
#define KCODES 1024
#define ZQ_ELEMS (BATCH*DIM*TLEN)  // 16777216
#define MARGIN 0.25f

// ---------------- device scratch (static; no allocations allowed) ----------
__device__ float d_e2[KCODES];
__device__ int   d_counts[KCODES];
__device__ float d_sumd2;
__device__ int   d_idx[NROWS];
__device__ float d_x2[NROWS];
__device__ int   d_nflag;
__device__ int   d_flagrows[NROWS];
__device__ unsigned long long d_rkey[NROWS];
__device__ float d_xhi[(size_t)NROWS * DIM];   // 64 MiB, mma-fragment order
__device__ float d_xt [(size_t)NROWS * DIM];   // 64 MiB, exact fp32 row-major
__device__ float d_ehi[KCODES * DIM];

// ---------------- helpers ----------------------------------------------------
__device__ __forceinline__ uint32_t smem_u32(const void* p) {
    return (uint32_t)__cvta_generic_to_shared(p);
}
__device__ __forceinline__ void cp16(uint32_t dst, const void* src) {
    asm volatile("cp.async.cg.shared.global [%0], [%1], 16;" :: "r"(dst), "l"(src));
}
__device__ __forceinline__ float tf32r(float v) {
    uint32_t r;
    asm("cvt.rna.tf32.f32 %0, %1;" : "=r"(r) : "f"(v));
    return __uint_as_float(r);
}
// order-preserving float -> u32 (ascending) and inverse
__device__ __forceinline__ uint32_t fkey(float v) {
    uint32_t u = __float_as_uint(v);
    return (u & 0x80000000u) ? ~u : (u | 0x80000000u);
}
__device__ __forceinline__ float funkey(uint32_t u) {
    return __uint_as_float((u & 0x80000000u) ? (u ^ 0x80000000u) : ~u);
}
__device__ __forceinline__ unsigned long long pkey(float v, int ix) {
    return ((unsigned long long)fkey(v) << 32) | (unsigned)ix;
}

// D += A * B  (m16n8k8, tf32 inputs as .b32 bit patterns, fp32 accum)
#define MMA_TF32(c, a, b) \
    asm volatile("mma.sync.aligned.m16n8k8.row.col.f32.tf32.tf32.f32 " \
        "{%0,%1,%2,%3}, {%4,%5,%6,%7}, {%8,%9}, {%0,%1,%2,%3};" \
        : "+f"((c)[0]), "+f"((c)[1]), "+f"((c)[2]), "+f"((c)[3]) \
        : "r"((a).x), "r"((a).y), "r"((a).z), "r"((a).w), \
          "r"((b).x), "r"((b).y))

// ---------------- smem layout of vq_mma --------------------------------------
#define OFF_AHI   0
#define OFF_BHI   16384
#define STG       32768
#define SM_E2     0
#define SM_BSUM   4096
#define SM_SKEY1  4352       // 128 x u64
#define SM_SKEY2  5376       // 128 x u64
#define SM_STAGE  6400
#define SMEM_MMA  (SM_STAGE + 2*STG)   // 71936 B

// ---------------- pre-pass: codebook pack + norms + zero stats ---------------
__global__ __launch_bounds__(256)
void vq_pack_e(const float* __restrict__ e) {
    const int tid = threadIdx.x, wid = tid >> 5, lane = tid & 31;
    const int nt = blockIdx.x;             // 128 ntiles of 8 codes
    const int n = nt * 8 + (lane >> 2);
    #pragma unroll
    for (int q = 0; q < 4; q++) {
        int kt = wid * 4 + q;
        int k = kt * 8 + (lane & 3);
        float v0 = e[(size_t)n * DIM + k];
        float v1 = e[(size_t)n * DIM + k + 4];
        size_t o = (((size_t)nt * 32 + kt) * 32 + lane) * 2;
        *(float2*)(d_ehi + o) = make_float2(tf32r(v0), tf32r(v1));
    }
    {
        int code = nt * 8 + wid;
        float s = 0.f;
        #pragma unroll
        for (int j = 0; j < 8; j++) {
            float v = e[(size_t)code * DIM + lane + 32 * j];
            s += v * v;
        }
        #pragma unroll
        for (int o = 16; o; o >>= 1) s += __shfl_down_sync(0xffffffffu, s, o);
        if (lane == 0) { d_e2[code] = s; d_counts[code] = 0; }
    }
    if (blockIdx.x == 0 && tid == 0) { d_sumd2 = 0.f; d_nflag = 0; }
}

// ---------------- pre-pass: x transpose + tf32 hi + exact copy + norms -------
__global__ __launch_bounds__(256)
void vq_pack_x(const float* __restrict__ x) {
    __shared__ float sm[DIM][33];
    const int tid = threadIdx.x;
    const int b  = blockIdx.x >> 7;
    const int t0 = (blockIdx.x & 127) * 32;
    const int tx = tid & 31, ty = tid >> 5;
    const float* src = x + (size_t)b * DIM * TLEN + t0 + tx;
    #pragma unroll
    for (int dd = 0; dd < 32; dd++) {
        int d = dd * 8 + ty;
        sm[d][tx] = src[(size_t)d * TLEN];
    }
    __syncthreads();

    // row norms (8 threads per row)
    {
        const int half = tid & 7, r = tid >> 3;
        float part = 0.f;
        #pragma unroll 8
        for (int kk = 0; kk < 32; kk++) {
            float v = sm[half * 32 + kk][r];
            part += v * v;
        }
        #pragma unroll
        for (int o = 4; o; o >>= 1) part += __shfl_down_sync(0xffffffffu, part, o);
        if (half == 0) d_x2[(size_t)b * TLEN + t0 + r] = part;
    }

    // exact row-major transposed copy (for rescore; coalesced)
    {
        const size_t row0 = (size_t)b * TLEN + t0;
        #pragma unroll
        for (int j = 0; j < 32; j++) {
            int i = tid + 256 * j;
            int r = i >> 8, d = i & 255;
            d_xt[(row0 + r) * DIM + d] = sm[d][r];
        }
    }

    // fragment packing: 2 mtiles x 32 kt x 32 lanes = 2048 float4
    const int mt0 = blockIdx.x * 2;
    #pragma unroll
    for (int j = 0; j < 8; j++) {
        int i = tid + 256 * j;
        int lane = i & 31, kt = (i >> 5) & 31, mtl = i >> 10;
        int tr = mtl * 16 + (lane >> 2);
        int k0 = kt * 8 + (lane & 3);
        float4 hv = make_float4(tf32r(sm[k0][tr]),     tf32r(sm[k0][tr + 8]),
                                tf32r(sm[k0 + 4][tr]), tf32r(sm[k0 + 4][tr + 8]));
        size_t o = (((size_t)(mt0 + mtl) * 32 + kt) * 32 + lane) * 4;
        *(float4*)(d_xhi + o) = hv;
    }
}

// ---------------- stage copy (cp.async, hi-only) ------------------------------
__device__ __forceinline__ void stage_copy(uint32_t sbase, int tid, int mt0, int it, int buf) {
    const int nc = it >> 3, kc = it & 7;
    const uint32_t stg = sbase + SM_STAGE + buf * STG;
    // A: 8 mt x 4 kt x 32 lanes x 16B
    #pragma unroll
    for (int j = 0; j < 4; j++) {
        int i = tid + 256 * j;
        int lane = i & 31, kt = (i >> 5) & 3, mt = i >> 7;
        size_t g = (((size_t)(mt0 + mt) * 32 + kc * 4 + kt) * 32 + lane) * 4;
        cp16(stg + OFF_AHI + ((mt * 4 + kt) * 32 + lane) * 16, d_xhi + g);
    }
    // B: 16 nt x 4 kt x 16 lane-pairs x 16B
    #pragma unroll
    for (int j = 0; j < 4; j++) {
        int i = tid + 256 * j;
        int lp = i & 15, kt = (i >> 4) & 3, nt = i >> 6;
        size_t g = (((size_t)(nc * 16 + nt) * 32 + kc * 4 + kt) * 32 + lp * 2) * 2;
        cp16(stg + OFF_BHI + ((nt * 4 + kt) * 32 + lp * 2) * 8, d_ehi + g);
    }
    asm volatile("cp.async.commit_group;");
}

// ---------------- main: 1-pass hi.hi TF32 GEMM + top-2 argmin ----------------
__global__ __launch_bounds__(256, 2)
void vq_mma() {
    extern __shared__ char smem[];
    const uint32_t sb = smem_u32(smem);
    float* e2s = (float*)smem;
    float* bsum = (float*)(smem + SM_BSUM);
    unsigned long long* skey1 = (unsigned long long*)(smem + SM_SKEY1);
    unsigned long long* skey2 = (unsigned long long*)(smem + SM_SKEY2);
    const int tid = threadIdx.x, wid = tid >> 5, lane = tid & 31;
    const int wm = wid & 3, wn = wid >> 2;       // warp grid 4(M) x 2(N)
    const int row0 = blockIdx.x * 128;
    const int mt0  = blockIdx.x * 8;

    stage_copy(sb, tid, mt0, 0, 0);              // prefetch stage 0 ASAP
    for (int i = tid; i < KCODES; i += 256) e2s[i] = d_e2[i];
    if (tid < 128) { skey1[tid] = ~0ull; skey2[tid] = ~0ull; }
    if (tid == 0) *bsum = 0.f;

    float b1[4], b2[4];
    int   i1[4], i2[4];
    #pragma unroll
    for (int s = 0; s < 4; s++) { b1[s] = INFINITY; b2[s] = INFINITY; i1[s] = 0; i2[s] = 0; }

    float acc[2][8][4];

    for (int it = 0; it < 64; it++) {
        if (it + 1 < 64) {
            stage_copy(sb, tid, mt0, it + 1, (it + 1) & 1);
            asm volatile("cp.async.wait_group 1;");
        } else {
            asm volatile("cp.async.wait_group 0;");
        }
        __syncthreads();

        const int kc = it & 7, nc = it >> 3;
        if (kc == 0) {
            #pragma unroll
            for (int m = 0; m < 2; m++)
                #pragma unroll
                for (int n = 0; n < 8; n++)
                    #pragma unroll
                    for (int q = 0; q < 4; q++) acc[m][n][q] = 0.f;
        }

        const char* stg = smem + SM_STAGE + (it & 1) * STG;
        #pragma unroll
        for (int kt = 0; kt < 4; kt++) {
            uint4 ah[2];
            #pragma unroll
            for (int m = 0; m < 2; m++) {
                int mt = wm * 2 + m;
                ah[m] = *(const uint4*)(stg + OFF_AHI + ((mt * 4 + kt) * 32 + lane) * 16);
            }
            #pragma unroll
            for (int n = 0; n < 8; n++) {
                int nt = wn * 8 + n;
                uint2 bh = *(const uint2*)(stg + OFF_BHI + ((nt * 4 + kt) * 32 + lane) * 8);
                #pragma unroll
                for (int m = 0; m < 2; m++) MMA_TF32(acc[m][n], ah[m], bh);
            }
        }
        __syncthreads();

        if (kc == 7) {
            // finalize chunk: score = ||e||^2 - 2*dot; track top-2 per slot
            #pragma unroll
            for (int n = 0; n < 8; n++) {
                const int n0 = nc * 128 + wn * 64 + n * 8 + 2 * (lane & 3);
                const float e20 = e2s[n0], e21 = e2s[n0 + 1];
                #pragma unroll
                for (int m = 0; m < 2; m++) {
                    #pragma unroll
                    for (int q = 0; q < 4; q++) {
                        const int s = m * 2 + (q >> 1);
                        const int ix = n0 + (q & 1);
                        float sc = fmaf(-2.f, acc[m][n][q], (q & 1) ? e21 : e20);
                        if (sc < b1[s]) {
                            b2[s] = b1[s]; i2[s] = i1[s];
                            b1[s] = sc;    i1[s] = ix;
                        } else if (sc < b2[s]) {
                            b2[s] = sc;    i2[s] = ix;
                        }
                    }
                }
            }
        }
    }

    // top-2 merge across quad lanes, then across wn halves via two-stage
    // shared atomicMin on packed keys. Lower idx wins ties (jnp.argmin).
    #pragma unroll
    for (int s = 0; s < 4; s++) {
        unsigned long long k1 = pkey(b1[s], i1[s]);
        unsigned long long k2 = pkey(b2[s], i2[s]);
        #pragma unroll
        for (int o = 1; o <= 2; o <<= 1) {
            unsigned long long ok1 = __shfl_xor_sync(0xffffffffu, k1, o);
            unsigned long long ok2 = __shfl_xor_sync(0xffffffffu, k2, o);
            if (ok1 < k1) { k2 = (k1 < ok2) ? k1 : ok2; k1 = ok1; }
            else          { k2 = (k2 < ok1) ? k2 : ok1; }
        }
        if ((lane & 3) == 0) {
            int lrow = wm * 32 + (s >> 1) * 16 + (s & 1) * 8 + (lane >> 2);
            atomicMin(&skey1[lrow], k1);
            b1[s] = __uint_as_float((uint32_t)(k1 >> 32)); i1[s] = (int)(k1 & 0xffffffffull);
            b2[s] = __uint_as_float((uint32_t)(k2 >> 32)); i2[s] = (int)(k2 & 0xffffffffull);
        }
    }
    __syncthreads();
    #pragma unroll
    for (int s = 0; s < 4; s++) {
        if ((lane & 3) == 0) {
            int lrow = wm * 32 + (s >> 1) * 16 + (s & 1) * 8 + (lane >> 2);
            unsigned long long k1 = ((unsigned long long)__float_as_uint(b1[s]) << 32) | (unsigned)i1[s];
            unsigned long long k2 = ((unsigned long long)__float_as_uint(b2[s]) << 32) | (unsigned)i2[s];
            atomicMin(&skey2[lrow], k2);
            if (k1 != skey1[lrow]) atomicMin(&skey2[lrow], k1);
        }
    }
    __syncthreads();

    if (tid < 128) {
        unsigned long long k1 = skey1[tid], k2 = skey2[tid];
        float v1 = funkey((uint32_t)(k1 >> 32));
        float v2 = funkey((uint32_t)(k2 >> 32));
        int   ix = (int)(k1 & 0xffffffffull);
        const int row = row0 + tid;
        float lsum = 0.f;
        if (v2 - v1 >= MARGIN) {
            d_idx[row] = ix;
            atomicAdd(&d_counts[ix], 1);
            lsum = d_x2[row] + v1;             // ||x - e||^2 (hi approx, loss only)
        } else {
            int slot = atomicAdd(&d_nflag, 1);
            d_flagrows[slot] = row;
            d_rkey[row] = ~0ull;
            d_idx[row] = ix;                   // provisional; rescore overwrites
        }
        #pragma unroll
        for (int o = 16; o; o >>= 1) lsum += __shfl_down_sync(0xffffffffu, lsum, o);
        if (lane == 0) atomicAdd(bsum, lsum);
    }
    __syncthreads();
    if (tid == 0) atomicAdd(&d_sumd2, *bsum);
}

// ---------------- exact fp32 rescore, GEMM-tiled ------------------------------
// grid (96, 16): y-block owns 64 codes (staged once in smem), x strides over
// 16-row flag groups. thread = (code cl=tid>>2, rows rg+4i, rg=tid&3).
#define RS_G 16
#define RS_PITCH 260
#define RS_SMEM ((64*RS_PITCH + RS_G*RS_PITCH)*4 + 128)   // 83328 B

__global__ __launch_bounds__(256)
void vq_rescore(const float* __restrict__ embed) {
    extern __shared__ float rsm[];
    float* es = rsm;                           // [64][260]
    float* xs = rsm + 64 * RS_PITCH;           // [16][260]
    unsigned long long* sk = (unsigned long long*)(rsm + (64 + RS_G) * RS_PITCH);
    const int nf = d_nflag;
    if ((int)blockIdx.x * RS_G >= nf) return;
    const int tid = threadIdx.x, lane = tid & 31;
    const int c0 = blockIdx.y * 64;
    const int cl = tid >> 2;                   // local code 0..63
    const int rg = tid & 3;                    // row phase
    const int c  = c0 + cl;
    const float e2v = d_e2[c];
    const uint32_t sb = smem_u32(rsm);

    // stage embed chunk once (64 codes x 256 dims), coalesced cp.async
    #pragma unroll
    for (int j = 0; j < 16; j++) {
        int i = tid + 256 * j;
        int row = i >> 6, q = i & 63;
        cp16(sb + (row * RS_PITCH + q * 4) * 4,
             embed + (size_t)(c0 + row) * DIM + q * 4);
    }
    asm volatile("cp.async.commit_group;");

    for (int g0 = blockIdx.x * RS_G; g0 < nf; g0 += gridDim.x * RS_G) {
        const int nr = min(RS_G, nf - g0);
        if (tid < RS_G) sk[tid] = ~0ull;
        for (int i = tid; i < nr * 64; i += 256) {
            int r = i >> 6, q = i & 63;
            cp16(sb + ((64 + r) * RS_PITCH + q * 4) * 4,
                 d_xt + (size_t)d_flagrows[g0 + r] * DIM + q * 4);
        }
        asm volatile("cp.async.commit_group;");
        asm volatile("cp.async.wait_group 0;");
        __syncthreads();

        float dots[4] = {0.f, 0.f, 0.f, 0.f};
        #pragma unroll 8
        for (int d = 0; d < 256; d += 4) {
            float4 e4 = *(const float4*)&es[cl * RS_PITCH + d];
            #pragma unroll
            for (int i = 0; i < 4; i++) {
                float4 x4 = *(const float4*)&xs[(rg + 4 * i) * RS_PITCH + d];
                dots[i] = fmaf(e4.x, x4.x, fmaf(e4.y, x4.y,
                          fmaf(e4.z, x4.z, fmaf(e4.w, x4.w, dots[i]))));
            }
        }

        // reduce min over the 8 codes in each warp, then across warps via smem
        #pragma unroll
        for (int i = 0; i < 4; i++) {
            unsigned long long k = pkey(fmaf(-2.f, dots[i], e2v), c);
            #pragma unroll
            for (int o = 4; o <= 16; o <<= 1) {
                unsigned long long ok = __shfl_xor_sync(0xffffffffu, k, o);
                if (ok < k) k = ok;
            }
            if (lane < 4) atomicMin(&sk[lane + 4 * i], k);
        }
        __syncthreads();
        if (tid < nr) atomicMin(&d_rkey[d_flagrows[g0 + tid]], sk[tid]);
        __syncthreads();
    }
}

// ---------------- fixup: commit rescored rows --------------------------------
__global__ __launch_bounds__(256)
void vq_fixup() {
    __shared__ float red[32];
    const int tid = threadIdx.x, lane = tid & 31;
    const int nf = d_nflag;
    float ls = 0.f;
    for (int i = tid; i < nf; i += 256) {
        int row = d_flagrows[i];
        unsigned long long k = d_rkey[row];
        int ix = (int)(k & 0xffffffffull);
        d_idx[row] = ix;
        atomicAdd(&d_counts[ix], 1);
        ls += d_x2[row] + funkey((uint32_t)(k >> 32));
    }
    #pragma unroll
    for (int o = 16; o; o >>= 1) ls += __shfl_down_sync(0xffffffffu, ls, o);
    if (lane == 0) red[tid >> 5] = ls;
    __syncthreads();
    if (tid < 32) {
        float v = (tid < 8) ? red[tid] : 0.f;
        #pragma unroll
        for (int o = 4; o; o >>= 1) v += __shfl_down_sync(0xffffffffu, v, o);
        if (tid == 0) atomicAdd(&d_sumd2, v);
    }
}

// ---------------- gather codewords, write z_q in (B, D, T) layout ------------
__global__ __launch_bounds__(256)
void vq_gather(const float* __restrict__ embed, float* __restrict__ out) {
    __shared__ float sh[DIM * 33];             // [d][t] layout, padded
    __shared__ int sidx[32];
    const int tid = threadIdx.x;
    const int row0 = blockIdx.x * 32;
    const int b = row0 >> 12, t0 = row0 & (TLEN - 1);

    if (tid < 32) sidx[tid] = d_idx[row0 + tid];
    __syncthreads();
    #pragma unroll
    for (int j = 0; j < 32; j++) {
        int i = tid + 256 * j;
        int r = i >> 8, d = i & 255;
        sh[d * 33 + r] = embed[(size_t)sidx[r] * DIM + d];
    }
    __syncthreads();
    float* ob = out + (size_t)b * DIM * TLEN + t0;
    #pragma unroll
    for (int j = 0; j < 8; j++) {
        int i = tid + 256 * j;
        int tl4 = (i & 7) * 4, d = i >> 3;
        float4 v = make_float4(sh[d * 33 + tl4],     sh[d * 33 + tl4 + 1],
                               sh[d * 33 + tl4 + 2], sh[d * 33 + tl4 + 3]);
        *(float4*)(ob + (size_t)d * TLEN + tl4) = v;
    }
}

// ---------------- scalars: loss, kldiv_r, perplexity -------------------------
__global__ void vq_finalize(float* __restrict__ out, int out_size) {
    __shared__ float red[32];
    const int tid = threadIdx.x;   // 1024 threads
    float p = (float)d_counts[tid] * (1.0f / (float)NROWS);
    float term = p * logf(p + 1e-10f);
    #pragma unroll
    for (int off = 16; off; off >>= 1) term += __shfl_down_sync(0xffffffffu, term, off);
    if ((tid & 31) == 0) red[tid >> 5] = term;
    __syncthreads();
    if (tid < 32) {
        float v = red[tid];
        #pragma unroll
        for (int off = 16; off; off >>= 1) v += __shfl_down_sync(0xffffffffu, v, off);
        if (tid == 0) {
            float perp = expf(-v);
            float loss = 1.25f * d_sumd2 * (1.0f / (float)ZQ_ELEMS);
            float kld  = (float)(log((double)KCODES) * (double)TLEN);
            int Z = ZQ_ELEMS;
            if (Z < out_size) out[Z] = loss;
            for (int i = 0; i < BATCH; i++)
                if (Z + 1 + i < out_size) out[Z + 1 + i] = kld;
            if (Z + 17 < out_size) out[Z + 17] = perp;
        }
    }
}

// ---------------- launcher ----------------------------------------------------
extern "C" void kernel_launch(void* const* d_in, const int* in_sizes, int n_in,
                              void* d_out, int out_size) {
    const float* a0 = (const float*)d_in[0];
    const float* a1 = (const float*)d_in[1];
    const float* x;
    const float* embed;
    if (in_sizes[0] == ZQ_ELEMS) { x = a0; embed = a1; }
    else                         { x = a1; embed = a0; }
    float* out = (float*)d_out;

    cudaFuncSetAttribute(vq_mma, cudaFuncAttributeMaxDynamicSharedMemorySize, SMEM_MMA);
    cudaFuncSetAttribute(vq_rescore, cudaFuncAttributeMaxDynamicSharedMemorySize, RS_SMEM);

    vq_pack_e<<<KCODES / 8, 256>>>(embed);
    vq_pack_x<<<BATCH * (TLEN / 32), 256>>>(x);
    vq_mma<<<NROWS / 128, 256, SMEM_MMA>>>();
    vq_rescore<<<dim3(96, 16), 256, RS_SMEM>>>(embed);
    vq_fixup<<<1, 256>>>();
    vq_gather<<<NROWS / 32, 256>>>(embed, out);
    vq_finalize<<<1, KCODES>>>(out, out_size);
}